// round 11
// baseline (speedup 1.0000x reference)
#include <cuda_runtime.h>
#include <math.h>
#include <stdint.h>

typedef unsigned long long u64;

// ============================================================
// Scratch (device globals -- no allocation allowed)
// ============================================================
__device__ float g_h1 [33554432];  // [16,128,128,128]
__device__ float g_a  [16777216];  // [16,256,64,64]
__device__ float g_b  [16777216];  // [16,256,64,64]
__device__ float g_mid[ 2097152];  // [16,32,64,64]
__device__ float g_wT [2304*256];  // transposed weights [K][Cout]
__device__ float g_part[256 * 4];
__device__ int   g_cnt [4 * 512];

// Output layout (tuple order): x_recon | rq_loss | z_q | z_e | perps
#define OFF_XREC 0
#define OFF_LOSS 3145728
#define OFF_ZQ   3145729
#define OFF_ZE   7340033
#define OFF_PERP 11534337

#define BK 8
#define KMAX 2304

// ---- packed fp32x2 helpers (FFMA2 path) ----
__device__ __forceinline__ u64 pack2(float x){
    u64 r; asm("mov.b64 %0, {%1, %1};" : "=l"(r) : "f"(x)); return r;
}
__device__ __forceinline__ void fma2(u64& acc, u64 a, u64 b){
    asm("fma.rn.f32x2 %0, %1, %2, %0;" : "+l"(acc) : "l"(a), "l"(b));
}
__device__ __forceinline__ float2 unpack2(u64 v){
    float2 f; asm("mov.b64 {%0, %1}, %2;" : "=f"(f.x), "=f"(f.y) : "l"(v)); return f;
}

struct ConvParams {
    const float* in; const float* bias; const float* residual; float* out;
    int Cin, IH, IW, Cout, OH, OW;
    int KHW, KW, Kdim;
    int stride, padH, padW;
    int OHfull, OWfull, oyOff, oyStep, oxOff, oxStep;
    int inRelu, outRelu, addRes;
};

// ============================================================
// Weight transpose: w (arbitrary tap strides) -> wT[k][Cout]
// ============================================================
__global__ void wtrans_kernel(const float* __restrict__ w, float* __restrict__ wT,
                              int Cout, int Kdim, int KHW, int KW,
                              int wsCo, int wsCi, int wsKy,
                              int kyOff, int kyStep, int kxOff, int kxStep)
{
    int idx = blockIdx.x * 256 + threadIdx.x;
    if (idx >= Kdim * Cout) return;
    int k = idx / Cout, m = idx - k * Cout;
    int ci = k / KHW, r2 = k - ci * KHW;
    int ky = r2 / KW, kx = r2 - ky * KW;
    wT[idx] = w[m * wsCo + ci * wsCi + (kyOff + ky * kyStep) * wsKy + kxOff + kx * kxStep];
}

// ============================================================
// Implicit-GEMM conv, double-buffered, BN=128, FFMA2 microkernel
// Warp geometry: 4 tym x 8 txn per warp (balanced smem traffic)
// ============================================================
template<int BM, int TM, int TN>
__global__ __launch_bounds__(256, 2) void conv_gemm5(ConvParams p, const float* __restrict__ wT)
{
    constexpr int XG = 128 / TN;         // txn groups total
    constexpr int NP = TN / 2;           // packed pairs along N
    constexpr int WX = XG / 8;           // warps along txn
    __shared__ __align__(16) float As[2][BK][BM + 4];
    __shared__ __align__(16) float Bs[2][BK][128 + 4];
    __shared__ int sBOff[KMAX];
    __shared__ int sKyx [KMAX];

    const int tid  = threadIdx.x;
    const int Kdim = p.Kdim;

    for (int k = tid; k < Kdim; k += 256) {
        int ci = k / p.KHW, r2 = k - ci * p.KHW;
        int ky = r2 / p.KW, kx = r2 - ky * p.KW;
        sBOff[k] = (ci * p.IH + ky) * p.IW + kx;
        sKyx[k]  = (ky << 16) | kx;
    }

    const int lk   = tid >> 5;           // k-row for loaders
    const int ln4  = (tid & 31) << 2;    // 4 B-cols per thread
    const int OHOW = p.OH * p.OW;
    const int Cout = p.Cout;
    const int mBase = blockIdx.x * BM;

    // B-column precompute (4 cols per thread)
    int inB[4], iy0a[4], ix0a[4];
    {
        int colBase = blockIdx.y * 128 + ln4;
#pragma unroll
        for (int j = 0; j < 4; j++) {
            int col = colBase + j;
            int n2 = col / OHOW; int rr = col - n2 * OHOW;
            int oy = rr / p.OW;  int ox = rr - oy * p.OW;
            int iy0 = oy * p.stride - p.padH;
            int ix0 = ox * p.stride - p.padW;
            iy0a[j] = iy0; ix0a[j] = ix0;
            inB[j]  = (n2 * p.Cin * p.IH + iy0) * p.IW + ix0;
        }
    }

    u64 acc[TM][NP];
#pragma unroll
    for (int i = 0; i < TM; i++)
#pragma unroll
        for (int j = 0; j < NP; j++) acc[i][j] = 0ull;

    float4 aR, bR;

    auto loadA = [&](int k0) {
        int kg = k0 + lk;
        if constexpr (BM == 128) {
            aR = *(const float4*)(wT + (size_t)kg * Cout + mBase + ((tid & 31) << 2));
        } else if constexpr (BM == 64) {
            const float2 t2 = *(const float2*)(wT + (size_t)kg * Cout + mBase + ((tid & 31) << 1));
            aR.x = t2.x; aR.y = t2.y;
        } else {
            aR.x = wT[(size_t)kg * Cout + mBase + (tid & 31)];
        }
    };
    auto loadB = [&](int k0) {
        int kg = k0 + lk;
        int off = sBOff[kg];
        int kyx = sKyx[kg];
        int ky = kyx >> 16, kx = kyx & 0xffff;
        float v[4];
#pragma unroll
        for (int j = 0; j < 4; j++) {
            int iy = iy0a[j] + ky, ix = ix0a[j] + kx;
            float t = 0.f;
            if ((unsigned)iy < (unsigned)p.IH && (unsigned)ix < (unsigned)p.IW) {
                t = __ldg(p.in + inB[j] + off);
                if (p.inRelu) t = fmaxf(t, 0.f);
            }
            v[j] = t;
        }
        bR = make_float4(v[0], v[1], v[2], v[3]);
    };
    auto store = [&](int buf) {
        if constexpr (BM == 128) {
            *(float4*)&As[buf][lk][(tid & 31) << 2] = aR;
        } else if constexpr (BM == 64) {
            int m2 = (tid & 31) << 1;
            As[buf][lk][m2] = aR.x; As[buf][lk][m2 + 1] = aR.y;
        } else {
            As[buf][lk][tid & 31] = aR.x;
        }
        *(float4*)&Bs[buf][lk][ln4] = bR;
    };

    __syncthreads();          // tables ready
    loadA(0); loadB(0); store(0);
    __syncthreads();

    const int nkb = Kdim / BK;
    // Balanced warp geometry: 4 tym x 8 txn per warp
    const int wid  = tid >> 5, lane = tid & 31;
    const int tym  = (wid / WX) * 4 + (lane >> 3);
    const int txn  = (wid % WX) * 8 + (lane & 7);

    for (int kb = 0; kb < nkb; kb++) {
        int cur = kb & 1;
        if (kb + 1 < nkb) { loadA((kb + 1) * BK); loadB((kb + 1) * BK); }
#pragma unroll
        for (int kk = 0; kk < BK; kk++) {
            float a[TM];
            u64 pb[NP];
#pragma unroll
            for (int s = 0; s < TM / 4; s++)
                *(float4*)&a[s * 4] = *(const float4*)&As[cur][kk][tym * TM + s * 4];
#pragma unroll
            for (int u = 0; u < NP / 2; u++) {
                ulonglong2 t = *(const ulonglong2*)&Bs[cur][kk][txn * TN + u * 4];
                pb[u * 2] = t.x; pb[u * 2 + 1] = t.y;
            }
#pragma unroll
            for (int i = 0; i < TM; i++) {
                u64 pa = pack2(a[i]);
#pragma unroll
                for (int j = 0; j < NP; j++)
                    fma2(acc[i][j], pa, pb[j]);
            }
        }
        if (kb + 1 < nkb) store(cur ^ 1);
        __syncthreads();
    }

    // Epilogue: bias (+residual) (+relu), strided/offset output
    int colNC[TN], colRow[TN];
#pragma unroll
    for (int j = 0; j < TN; j++) {
        int col = blockIdx.y * 128 + txn * TN + j;
        int n2 = col / OHOW; int rr = col - n2 * OHOW;
        int oy = rr / p.OW;  int ox = rr - oy * p.OW;
        colNC[j]  = n2 * Cout;
        colRow[j] = (p.oyOff + oy * p.oyStep) * p.OWfull + p.oxOff + ox * p.oxStep;
    }
    const size_t plane = (size_t)p.OHfull * p.OWfull;
#pragma unroll
    for (int i = 0; i < TM; i++) {
        int m = mBase + tym * TM + i;
        float bi = __ldg(p.bias + m);
#pragma unroll
        for (int jp = 0; jp < NP; jp++) {
            float2 v2 = unpack2(acc[i][jp]);
            float vv[2] = {v2.x, v2.y};
#pragma unroll
            for (int h = 0; h < 2; h++) {
                int j = jp * 2 + h;
                float v = vv[h] + bi;
                size_t oidx = (size_t)(colNC[j] + m) * plane + colRow[j];
                if (p.addRes) v += __ldg(p.residual + oidx);
                if (p.outRelu) v = fmaxf(v, 0.f);
                p.out[oidx] = v;
            }
        }
    }
}

// ============================================================
// Dedicated conv_t2 (Cout=3): [16,128,128,128] -> [16,3,256,256]
// ============================================================
__global__ __launch_bounds__(256) void convt2_kernel(
    const float* __restrict__ in, const float* __restrict__ w,
    const float* __restrict__ bias, float* __restrict__ out)
{
    __shared__ float sw[3 * 128 * 16];
    const int tid = threadIdx.x;
    for (int i = tid; i < 6144; i += 256) sw[i] = w[i];
    __syncthreads();

    int idx = blockIdx.x * 256 + tid;
    int ox = idx & 255;
    int oy = (idx >> 8) & 255;
    int n  = idx >> 16;
    int py = oy & 1, px = ox & 1;
    int iyb = ((oy + py) >> 1) - 1;
    int ixb = ((ox + px) >> 1) - 1;

    float acc0 = __ldg(bias + 0), acc1 = __ldg(bias + 1), acc2 = __ldg(bias + 2);
    const float* inb = in + (size_t)n * 128 * 128 * 128;

    for (int ci = 0; ci < 128; ci++) {
        const float* ic = inb + ci * 16384;
#pragma unroll
        for (int ty = 0; ty < 2; ty++) {
            int iy = iyb + ty;
            if ((unsigned)iy < 128u) {
#pragma unroll
                for (int tx2 = 0; tx2 < 2; tx2++) {
                    int ix = ixb + tx2;
                    if ((unsigned)ix < 128u) {
                        float v  = __ldg(ic + iy * 128 + ix);
                        int   wi = (py + 2 * ty) * 4 + (px + 2 * tx2);
                        acc0 = fmaf(v, sw[(0 * 128 + ci) * 16 + wi], acc0);
                        acc1 = fmaf(v, sw[(1 * 128 + ci) * 16 + wi], acc1);
                        acc2 = fmaf(v, sw[(2 * 128 + ci) * 16 + wi], acc2);
                    }
                }
            }
        }
    }
    size_t base = (size_t)n * 3 * 65536 + oy * 256 + ox;
    out[base]             = acc0;
    out[base + 65536]     = acc1;
    out[base + 2 * 65536] = acc2;
}

// ============================================================
// Residual VQ (verified R1/R2)
// ============================================================
#define VQ_SMEM_BYTES ((512*64 + 512 + 512 + 32) * 4)

__global__ __launch_bounds__(256) void vq_kernel(
    const float* __restrict__ z_e, const float* __restrict__ codebooks,
    float* __restrict__ z_q, float* __restrict__ partial, int* __restrict__ counts)
{
    extern __shared__ float sh[];
    float* cb    = sh;
    float* cnorm = sh + 512 * 64;
    int*   hist  = (int*)(sh + 512 * 64 + 512);
    float* red   = sh + 512 * 64 + 512 + 512;

    const int tid = threadIdx.x;
    const int p   = blockIdx.x * 256 + tid;
    const int n   = p >> 12;
    const int hw  = p & 4095;
    const float* zp = z_e + (size_t)n * 262144 + hw;

    float r[64];
#pragma unroll
    for (int d = 0; d < 64; d++) r[d] = __ldg(zp + d * 4096);

    for (int level = 0; level < 4; level++) {
        const float4* src = (const float4*)(codebooks + (size_t)level * 32768);
        float4* dst = (float4*)cb;
        for (int i = tid; i < 8192; i += 256) dst[i] = src[i];
        hist[tid] = 0; hist[tid + 256] = 0;
        __syncthreads();
        for (int c = tid; c < 512; c += 256) {
            const float* cc = cb + c * 64;
            float s = 0.f;
#pragma unroll
            for (int d = 0; d < 64; d++) s = fmaf(cc[d], cc[d], s);
            cnorm[c] = s;
        }
        __syncthreads();

        float best = 3.0e38f; int bidx = 0;
        for (int c = 0; c < 512; c++) {
            const float4* cc = (const float4*)(cb + (c << 6));
            float d0 = 0.f, d1 = 0.f, d2 = 0.f, d3 = 0.f;
#pragma unroll
            for (int i = 0; i < 16; i++) {
                float4 v = cc[i];
                d0 = fmaf(v.x, r[4*i+0], d0);
                d1 = fmaf(v.y, r[4*i+1], d1);
                d2 = fmaf(v.z, r[4*i+2], d2);
                d3 = fmaf(v.w, r[4*i+3], d3);
            }
            float score = cnorm[c] - 2.f * ((d0 + d1) + (d2 + d3));
            if (score < best) { best = score; bidx = c; }
        }
        atomicAdd(&hist[bidx], 1);

        const float* q = cb + (bidx << 6);
        float lsum = 0.f;
#pragma unroll
        for (int d = 0; d < 64; d++) {
            float diff = q[d] - r[d];
            lsum = fmaf(diff, diff, lsum);
            r[d] = -diff;
        }
        float v = lsum;
#pragma unroll
        for (int o = 16; o > 0; o >>= 1) v += __shfl_xor_sync(0xffffffffu, v, o);
        if ((tid & 31) == 0) red[tid >> 5] = v;
        __syncthreads();
        if (tid == 0) {
            float t = 0.f;
            for (int i = 0; i < 8; i++) t += red[i];
            partial[blockIdx.x * 4 + level] = t;
        }
        atomicAdd(&counts[level * 512 + tid],       hist[tid]);
        atomicAdd(&counts[level * 512 + tid + 256], hist[tid + 256]);
        __syncthreads();
    }

    float* oq = z_q + (size_t)n * 262144 + hw;
#pragma unroll
    for (int d = 0; d < 64; d++) oq[d * 4096] = __ldg(zp + d * 4096) - r[d];
}

__global__ void vq_zero(float* partial, int* counts)
{
    int i = blockIdx.x * 256 + threadIdx.x;
    if (i < 1024) partial[i] = 0.f;
    if (i < 2048) counts[i]  = 0;
}

__global__ void vq_finalize(const float* __restrict__ partial, const int* __restrict__ counts,
                            float* __restrict__ out_loss, float* __restrict__ out_perp)
{
    __shared__ float losses[4];
    int tid = threadIdx.x;
    if (tid < 4) {
        float e = 0.f;
        for (int b = 0; b < 256; b++) e += partial[b * 4 + tid];
        e /= (65536.f * 64.f);
        losses[tid] = 0.25f * e;
        float s = 0.f;
        for (int c = 0; c < 512; c++) {
            float pr = (float)counts[tid * 512 + c] / 65536.f;
            s += pr * logf(pr + 1e-10f);
        }
        out_perp[tid] = expf(-s);
    }
    __syncthreads();
    if (tid == 0)
        out_loss[0] = 0.25f * (losses[0] + losses[1] + losses[2] + losses[3]);
}

// ============================================================
// Host-side launch helpers
// ============================================================
static float* s_wT = nullptr;

static void launch_conv(int cfg, ConvParams& p, const float* wT, int gx, int gy)
{
    dim3 g(gx, gy);
    if (cfg == 0)      conv_gemm5<128, 8, 8><<<g, 256>>>(p, wT);
    else if (cfg == 1) conv_gemm5< 64, 8, 4><<<g, 256>>>(p, wT);
    else               conv_gemm5< 32, 4, 4><<<g, 256>>>(p, wT);
}

static void conv2d(int cfg, const float* in, const float* w, const float* bias, const float* res,
                   float* out, int N, int Cin, int IH, int IW, int Cout, int OH, int OW,
                   int KH, int KW, int stride, int pad, bool inRelu, bool outRelu)
{
    int Kdim = Cin * KH * KW;
    wtrans_kernel<<<(Kdim * Cout + 255) / 256, 256>>>(
        w, s_wT, Cout, Kdim, KH * KW, KW,
        Cin * KH * KW, KH * KW, KW, 0, 1, 0, 1);

    ConvParams p;
    p.in = in; p.bias = bias; p.residual = res; p.out = out;
    p.Cin = Cin; p.IH = IH; p.IW = IW; p.Cout = Cout; p.OH = OH; p.OW = OW;
    p.KHW = KH * KW; p.KW = KW; p.Kdim = Kdim;
    p.stride = stride; p.padH = pad; p.padW = pad;
    p.OHfull = OH; p.OWfull = OW; p.oyOff = 0; p.oyStep = 1; p.oxOff = 0; p.oxStep = 1;
    p.inRelu = inRelu ? 1 : 0; p.outRelu = outRelu ? 1 : 0; p.addRes = (res != nullptr) ? 1 : 0;

    int BMsel = (cfg == 0) ? 128 : (cfg == 1) ? 64 : 32;
    launch_conv(cfg, p, s_wT, Cout / BMsel, (N * OH * OW) / 128);
}

// ConvTranspose2d(k=4,s=2,p=1) as 4 parity-class stride-1 2x2 convs
static void convT(const float* in, const float* w, const float* bias, float* out,
                  int N, int Cin, int IH, int IW, int Cout, bool inRelu, bool outRelu)
{
    int Kdim = Cin * 4;
    for (int py = 0; py < 2; py++)
        for (int px = 0; px < 2; px++) {
            float* wT = s_wT + (py * 2 + px) * Kdim * Cout;
            wtrans_kernel<<<(Kdim * Cout + 255) / 256, 256>>>(
                w, wT, Cout, Kdim, 4, 2,
                Cin * 16, 16, 4, py, 2, px, 2);

            ConvParams p;
            p.in = in; p.bias = bias; p.residual = nullptr; p.out = out;
            p.Cin = Cin; p.IH = IH; p.IW = IW; p.Cout = Cout; p.OH = IH; p.OW = IW;
            p.KHW = 4; p.KW = 2; p.Kdim = Kdim;
            p.stride = 1; p.padH = 1 - py; p.padW = 1 - px;
            p.OHfull = 2 * IH; p.OWfull = 2 * IW;
            p.oyOff = py; p.oyStep = 2; p.oxOff = px; p.oxStep = 2;
            p.inRelu = inRelu ? 1 : 0; p.outRelu = outRelu ? 1 : 0; p.addRes = 0;
            launch_conv(0, p, wT, Cout / 128, (N * IH * IW) / 128);
        }
}

extern "C" void kernel_launch(void* const* d_in, const int* in_sizes, int n_in,
                              void* d_out, int out_size)
{
    (void)in_sizes; (void)n_in; (void)out_size;

    const float* x       = (const float*)d_in[0];
    const float* enc_w1  = (const float*)d_in[1];
    const float* enc_b1  = (const float*)d_in[2];
    const float* enc_w2  = (const float*)d_in[3];
    const float* enc_b2  = (const float*)d_in[4];
    const float* enc_w3  = (const float*)d_in[5];
    const float* enc_b3  = (const float*)d_in[6];
    const float* enc_rw1 = (const float*)d_in[7];
    const float* enc_rb1 = (const float*)d_in[8];
    const float* enc_rw2 = (const float*)d_in[9];
    const float* enc_rb2 = (const float*)d_in[10];
    const float* enc_wp  = (const float*)d_in[11];
    const float* enc_bp  = (const float*)d_in[12];
    const float* dec_w1  = (const float*)d_in[13];
    const float* dec_b1  = (const float*)d_in[14];
    const float* dec_rw1 = (const float*)d_in[15];
    const float* dec_rb1 = (const float*)d_in[16];
    const float* dec_rw2 = (const float*)d_in[17];
    const float* dec_rb2 = (const float*)d_in[18];
    const float* t1w     = (const float*)d_in[19];
    const float* t1b     = (const float*)d_in[20];
    const float* t2w     = (const float*)d_in[21];
    const float* t2b     = (const float*)d_in[22];
    const float* cbs     = (const float*)d_in[23];

    float *h1, *ga, *gb, *gmid, *gpart; int* gcnt;
    cudaGetSymbolAddress((void**)&h1,    g_h1);
    cudaGetSymbolAddress((void**)&ga,    g_a);
    cudaGetSymbolAddress((void**)&gb,    g_b);
    cudaGetSymbolAddress((void**)&gmid,  g_mid);
    cudaGetSymbolAddress((void**)&s_wT,  g_wT);
    cudaGetSymbolAddress((void**)&gpart, g_part);
    cudaGetSymbolAddress((void**)&gcnt,  g_cnt);

    cudaFuncSetAttribute(vq_kernel, cudaFuncAttributeMaxDynamicSharedMemorySize, VQ_SMEM_BYTES);

    float* out    = (float*)d_out;
    float* o_xrec = out + OFF_XREC;
    float* o_loss = out + OFF_LOSS;
    float* o_zq   = out + OFF_ZQ;
    float* o_ze   = out + OFF_ZE;
    float* o_perp = out + OFF_PERP;

    // ---------------- Encoder ----------------
    conv2d(0, x,  enc_w1, enc_b1, nullptr, h1, 16,   3, 256, 256, 128, 128, 128, 4, 4, 2, 1, false, true);
    conv2d(0, h1, enc_w2, enc_b2, nullptr, ga, 16, 128, 128, 128, 256,  64,  64, 4, 4, 2, 1, false, true);
    conv2d(0, ga, enc_w3, enc_b3, nullptr, gb, 16, 256,  64,  64, 256,  64,  64, 3, 3, 1, 1, false, false);
    // res block 0
    conv2d(2, gb,   enc_rw1,         enc_rb1,       nullptr, gmid, 16, 256, 64, 64,  32, 64, 64, 3, 3, 1, 1, true, false);
    conv2d(0, gmid, enc_rw2,         enc_rb2,       gb,      ga,   16,  32, 64, 64, 256, 64, 64, 1, 1, 1, 0, true, false);
    // res block 1
    conv2d(2, ga,   enc_rw1 + 73728, enc_rb1 + 32,  nullptr, gmid, 16, 256, 64, 64,  32, 64, 64, 3, 3, 1, 1, true, false);
    conv2d(0, gmid, enc_rw2 + 8192,  enc_rb2 + 256, ga,      gb,   16,  32, 64, 64, 256, 64, 64, 1, 1, 1, 0, true, false);
    // projection (final res-stack relu folded into inRelu) -> z_e
    conv2d(1, gb, enc_wp, enc_bp, nullptr, o_ze, 16, 256, 64, 64, 64, 64, 64, 1, 1, 1, 0, true, false);

    // ---------------- Residual VQ ----------------
    vq_zero<<<8, 256>>>(gpart, gcnt);
    vq_kernel<<<256, 256, VQ_SMEM_BYTES>>>(o_ze, cbs, o_zq, gpart, gcnt);
    vq_finalize<<<1, 128>>>(gpart, gcnt, o_loss, o_perp);

    // ---------------- Decoder ----------------
    conv2d(0, o_zq, dec_w1, dec_b1, nullptr, ga, 16, 64, 64, 64, 256, 64, 64, 3, 3, 1, 1, false, false);
    // res block 0
    conv2d(2, ga,   dec_rw1,         dec_rb1,       nullptr, gmid, 16, 256, 64, 64,  32, 64, 64, 3, 3, 1, 1, true, false);
    conv2d(0, gmid, dec_rw2,         dec_rb2,       ga,      gb,   16,  32, 64, 64, 256, 64, 64, 1, 1, 1, 0, true, false);
    // res block 1
    conv2d(2, gb,   dec_rw1 + 73728, dec_rb1 + 32,  nullptr, gmid, 16, 256, 64, 64,  32, 64, 64, 3, 3, 1, 1, true, false);
    conv2d(0, gmid, dec_rw2 + 8192,  dec_rb2 + 256, gb,      ga,   16,  32, 64, 64, 256, 64, 64, 1, 1, 1, 0, true, false);
    // conv_t1 (final res-stack relu folded in) -> relu'd [16,128,128,128]
    convT(ga, t1w, t1b, h1, 16, 256, 64, 64, 128, true, true);
    // conv_t2 -> x_recon
    convt2_kernel<<<4096, 256>>>(h1, t2w, t2b, o_xrec);
}

// round 12
// speedup vs baseline: 1.0399x; 1.0399x over previous
#include <cuda_runtime.h>
#include <math.h>
#include <stdint.h>

typedef unsigned long long u64;

// ============================================================
// Scratch (device globals -- no allocation allowed)
// ============================================================
__device__ float g_h1 [33554432];  // [16,128,128,128]
__device__ float g_a  [16777216];  // [16,256,64,64]
__device__ float g_b  [16777216];  // [16,256,64,64]
__device__ float g_mid[ 2097152];  // [16,32,64,64]
__device__ float g_wT [2304*256];  // transposed weights [K][Cout]
__device__ float g_part[256 * 4];
__device__ int   g_cnt [4 * 512];

// Output layout (tuple order): x_recon | rq_loss | z_q | z_e | perps
#define OFF_XREC 0
#define OFF_LOSS 3145728
#define OFF_ZQ   3145729
#define OFF_ZE   7340033
#define OFF_PERP 11534337

#define BK 16
#define KMAX 2304

// ---- packed fp32x2 helpers (FFMA2 path) ----
__device__ __forceinline__ u64 pack2(float x){
    u64 r; asm("mov.b64 %0, {%1, %1};" : "=l"(r) : "f"(x)); return r;
}
__device__ __forceinline__ u64 packab(float a, float b){
    u64 r; asm("mov.b64 %0, {%1, %2};" : "=l"(r) : "f"(a), "f"(b)); return r;
}
__device__ __forceinline__ void fma2(u64& acc, u64 a, u64 b){
    asm("fma.rn.f32x2 %0, %1, %2, %0;" : "+l"(acc) : "l"(a), "l"(b));
}
__device__ __forceinline__ float2 unpack2(u64 v){
    float2 f; asm("mov.b64 {%0, %1}, %2;" : "=f"(f.x), "=f"(f.y) : "l"(v)); return f;
}

struct ConvParams {
    const float* in; const float* bias; const float* residual; float* out;
    int Cin, IH, IW, Cout, OH, OW;
    int KHW, KW, Kdim;
    int stride, padH, padW;
    int OHfull, OWfull, oyOff, oyStep, oxOff, oxStep;
    int inRelu, outRelu, addRes;
};

// ============================================================
// Weight transpose: w (arbitrary tap strides) -> wT[k][Cout]
// ============================================================
__global__ void wtrans_kernel(const float* __restrict__ w, float* __restrict__ wT,
                              int Cout, int Kdim, int KHW, int KW,
                              int wsCo, int wsCi, int wsKy,
                              int kyOff, int kyStep, int kxOff, int kxStep)
{
    int idx = blockIdx.x * 256 + threadIdx.x;
    if (idx >= Kdim * Cout) return;
    int k = idx / Cout, m = idx - k * Cout;
    int ci = k / KHW, r2 = k - ci * KHW;
    int ky = r2 / KW, kx = r2 - ky * KW;
    wT[idx] = w[m * wsCo + ci * wsCi + (kyOff + ky * kyStep) * wsKy + kxOff + kx * kxStep];
}

// ============================================================
// Implicit-GEMM conv, double-buffered, BN=128, BK=16, FFMA2
// ============================================================
template<int BM, int TM, int TN>
__global__ __launch_bounds__(256, 2) void conv_gemm6(ConvParams p, const float* __restrict__ wT)
{
    constexpr int NG = 128 / TN;         // n groups
    constexpr int NP = TN / 2;           // packed pairs along N
    __shared__ __align__(16) float As[2][BK][BM + 4];
    __shared__ __align__(16) float Bs[2][BK][128 + 4];
    __shared__ int sBOff[KMAX];
    __shared__ int sKyx [KMAX];

    const int tid  = threadIdx.x;
    const int Kdim = p.Kdim;

    for (int k = tid; k < Kdim; k += 256) {
        int ci = k / p.KHW, r2 = k - ci * p.KHW;
        int ky = r2 / p.KW, kx = r2 - ky * p.KW;
        sBOff[k] = (ci * p.IH + ky) * p.IW + kx;
        sKyx[k]  = (ky << 16) | kx;
    }

    const int lk   = tid >> 5;           // k-row base for loaders (rows lk, lk+8)
    const int ln4  = (tid & 31) << 2;    // 4 B-cols per thread
    const int OHOW = p.OH * p.OW;
    const int Cout = p.Cout;
    const int mBase = blockIdx.x * BM;

    // B-column precompute (4 cols per thread)
    int inB[4], iy0a[4], ix0a[4];
    {
        int colBase = blockIdx.y * 128 + ln4;
#pragma unroll
        for (int j = 0; j < 4; j++) {
            int col = colBase + j;
            int n2 = col / OHOW; int rr = col - n2 * OHOW;
            int oy = rr / p.OW;  int ox = rr - oy * p.OW;
            int iy0 = oy * p.stride - p.padH;
            int ix0 = ox * p.stride - p.padW;
            iy0a[j] = iy0; ix0a[j] = ix0;
            inB[j]  = (n2 * p.Cin * p.IH + iy0) * p.IW + ix0;
        }
    }

    u64 acc[TM][NP];
#pragma unroll
    for (int i = 0; i < TM; i++)
#pragma unroll
        for (int j = 0; j < NP; j++) acc[i][j] = 0ull;

    float4 aR[2], bR[2];

    auto loadA = [&](int k0) {
#pragma unroll
        for (int h = 0; h < 2; h++) {
            int kg = k0 + lk + h * 8;
            if constexpr (BM == 128) {
                aR[h] = *(const float4*)(wT + (size_t)kg * Cout + mBase + ((tid & 31) << 2));
            } else if constexpr (BM == 64) {
                const float2 t2 = *(const float2*)(wT + (size_t)kg * Cout + mBase + ((tid & 31) << 1));
                aR[h].x = t2.x; aR[h].y = t2.y;
            } else {
                aR[h].x = wT[(size_t)kg * Cout + mBase + (tid & 31)];
            }
        }
    };
    auto loadB = [&](int k0) {
#pragma unroll
        for (int h = 0; h < 2; h++) {
            int kg = k0 + lk + h * 8;
            int off = sBOff[kg];
            int kyx = sKyx[kg];
            int ky = kyx >> 16, kx = kyx & 0xffff;
            float v[4];
#pragma unroll
            for (int j = 0; j < 4; j++) {
                int iy = iy0a[j] + ky, ix = ix0a[j] + kx;
                float t = 0.f;
                if ((unsigned)iy < (unsigned)p.IH && (unsigned)ix < (unsigned)p.IW) {
                    t = __ldg(p.in + inB[j] + off);
                    if (p.inRelu) t = fmaxf(t, 0.f);
                }
                v[j] = t;
            }
            bR[h] = make_float4(v[0], v[1], v[2], v[3]);
        }
    };
    auto store = [&](int buf) {
#pragma unroll
        for (int h = 0; h < 2; h++) {
            if constexpr (BM == 128) {
                *(float4*)&As[buf][lk + h * 8][(tid & 31) << 2] = aR[h];
            } else if constexpr (BM == 64) {
                int m2 = (tid & 31) << 1;
                As[buf][lk + h * 8][m2] = aR[h].x; As[buf][lk + h * 8][m2 + 1] = aR[h].y;
            } else {
                As[buf][lk + h * 8][tid & 31] = aR[h].x;
            }
            *(float4*)&Bs[buf][lk + h * 8][ln4] = bR[h];
        }
    };

    __syncthreads();          // tables ready
    loadA(0); loadB(0); store(0);
    __syncthreads();

    const int nkb = Kdim / BK;
    const int tym = tid / NG;            // m group
    const int txn = tid % NG;            // n group

    for (int kb = 0; kb < nkb; kb++) {
        int cur = kb & 1;
        if (kb + 1 < nkb) { loadA((kb + 1) * BK); loadB((kb + 1) * BK); }
#pragma unroll
        for (int kk = 0; kk < BK; kk++) {
            float a[TM];
            u64 pb[NP];
#pragma unroll
            for (int s = 0; s < TM / 4; s++)
                *(float4*)&a[s * 4] = *(const float4*)&As[cur][kk][tym * TM + s * 4];
#pragma unroll
            for (int u = 0; u < NP / 2; u++) {
                ulonglong2 t = *(const ulonglong2*)&Bs[cur][kk][txn * TN + u * 4];
                pb[u * 2] = t.x; pb[u * 2 + 1] = t.y;
            }
#pragma unroll
            for (int i = 0; i < TM; i++) {
                u64 pa = pack2(a[i]);
#pragma unroll
                for (int j = 0; j < NP; j++)
                    fma2(acc[i][j], pa, pb[j]);
            }
        }
        if (kb + 1 < nkb) store(cur ^ 1);
        __syncthreads();
    }

    // Epilogue: bias (+residual) (+relu), strided/offset output
    int colNC[TN], colRow[TN];
#pragma unroll
    for (int j = 0; j < TN; j++) {
        int col = blockIdx.y * 128 + txn * TN + j;
        int n2 = col / OHOW; int rr = col - n2 * OHOW;
        int oy = rr / p.OW;  int ox = rr - oy * p.OW;
        colNC[j]  = n2 * Cout;
        colRow[j] = (p.oyOff + oy * p.oyStep) * p.OWfull + p.oxOff + ox * p.oxStep;
    }
    const size_t plane = (size_t)p.OHfull * p.OWfull;
#pragma unroll
    for (int i = 0; i < TM; i++) {
        int m = mBase + tym * TM + i;
        float bi = __ldg(p.bias + m);
#pragma unroll
        for (int jp = 0; jp < NP; jp++) {
            float2 v2 = unpack2(acc[i][jp]);
            float vv[2] = {v2.x, v2.y};
#pragma unroll
            for (int h = 0; h < 2; h++) {
                int j = jp * 2 + h;
                float v = vv[h] + bi;
                size_t oidx = (size_t)(colNC[j] + m) * plane + colRow[j];
                if (p.addRes) v += __ldg(p.residual + oidx);
                if (p.outRelu) v = fmaxf(v, 0.f);
                p.out[oidx] = v;
            }
        }
    }
}

// ============================================================
// Dedicated conv_t2 (Cout=3), FFMA2 for channels 0/1
// ============================================================
__global__ __launch_bounds__(256) void convt2_kernel(
    const float* __restrict__ in, const float* __restrict__ w,
    const float* __restrict__ bias, float* __restrict__ out)
{
    __shared__ u64   sw01[128 * 16];
    __shared__ float sw2 [128 * 16];
    const int tid = threadIdx.x;
    for (int i = tid; i < 2048; i += 256) {
        sw01[i] = packab(w[i], w[2048 + i]);
        sw2[i]  = w[4096 + i];
    }
    __syncthreads();

    int idx = blockIdx.x * 256 + tid;
    int ox = idx & 255;
    int oy = (idx >> 8) & 255;
    int n  = idx >> 16;
    int py = oy & 1, px = ox & 1;
    int iyb = ((oy + py) >> 1) - 1;
    int ixb = ((ox + px) >> 1) - 1;

    u64   acc01 = packab(__ldg(bias + 0), __ldg(bias + 1));
    float acc2  = __ldg(bias + 2);
    const float* inb = in + (size_t)n * 128 * 128 * 128;

    for (int ci = 0; ci < 128; ci++) {
        const float* ic = inb + ci * 16384;
#pragma unroll
        for (int ty = 0; ty < 2; ty++) {
            int iy = iyb + ty;
            if ((unsigned)iy < 128u) {
#pragma unroll
                for (int tx2 = 0; tx2 < 2; tx2++) {
                    int ix = ixb + tx2;
                    if ((unsigned)ix < 128u) {
                        float v  = __ldg(ic + iy * 128 + ix);
                        int   wi = ci * 16 + (py + 2 * ty) * 4 + (px + 2 * tx2);
                        fma2(acc01, pack2(v), sw01[wi]);
                        acc2 = fmaf(v, sw2[wi], acc2);
                    }
                }
            }
        }
    }
    float2 a01 = unpack2(acc01);
    size_t base = (size_t)n * 3 * 65536 + oy * 256 + ox;
    out[base]             = a01.x;
    out[base + 65536]     = a01.y;
    out[base + 2 * 65536] = acc2;
}

// ============================================================
// Residual VQ -- packed f32x2 distance loop (bit-identical order)
// ============================================================
#define VQ_SMEM_BYTES ((512*64 + 512 + 512 + 32) * 4)

__global__ __launch_bounds__(256) void vq_kernel(
    const float* __restrict__ z_e, const float* __restrict__ codebooks,
    float* __restrict__ z_q, float* __restrict__ partial, int* __restrict__ counts)
{
    extern __shared__ float sh[];
    float* cb    = sh;
    float* cnorm = sh + 512 * 64;
    int*   hist  = (int*)(sh + 512 * 64 + 512);
    float* red   = sh + 512 * 64 + 512 + 512;

    const int tid = threadIdx.x;
    const int p   = blockIdx.x * 256 + tid;
    const int n   = p >> 12;
    const int hw  = p & 4095;
    const float* zp = z_e + (size_t)n * 262144 + hw;

    // residual kept as packed pairs rp[j] = (r[2j], r[2j+1])
    u64 rp[32];
#pragma unroll
    for (int j = 0; j < 32; j++)
        rp[j] = packab(__ldg(zp + (2 * j) * 4096), __ldg(zp + (2 * j + 1) * 4096));

    for (int level = 0; level < 4; level++) {
        const float4* src = (const float4*)(codebooks + (size_t)level * 32768);
        float4* dst = (float4*)cb;
        for (int i = tid; i < 8192; i += 256) dst[i] = src[i];
        hist[tid] = 0; hist[tid + 256] = 0;
        __syncthreads();
        for (int c = tid; c < 512; c += 256) {
            const float* cc = cb + c * 64;
            float s = 0.f;
#pragma unroll
            for (int d = 0; d < 64; d++) s = fmaf(cc[d], cc[d], s);
            cnorm[c] = s;
        }
        __syncthreads();

        // argmin: d01 accumulates (d0,d1), d23 accumulates (d2,d3) -- bit-identical to scalar
        float best = 3.0e38f; int bidx = 0;
        for (int c = 0; c < 512; c++) {
            const u64* cc = (const u64*)(cb + (c << 6));
            u64 d01 = 0ull, d23 = 0ull;
#pragma unroll
            for (int i = 0; i < 16; i++) {
                fma2(d01, cc[2 * i],     rp[2 * i]);
                fma2(d23, cc[2 * i + 1], rp[2 * i + 1]);
            }
            float2 ax = unpack2(d01), bx = unpack2(d23);
            float score = cnorm[c] - 2.f * ((ax.x + ax.y) + (bx.x + bx.y));
            if (score < best) { best = score; bidx = c; }
        }
        atomicAdd(&hist[bidx], 1);

        // loss + residual update in original d-order (bit-identical)
        const float* q = cb + (bidx << 6);
        float lsum = 0.f;
#pragma unroll
        for (int j = 0; j < 32; j++) {
            float2 rr = unpack2(rp[j]);
            float d0 = q[2 * j]     - rr.x;
            lsum = fmaf(d0, d0, lsum);
            float d1 = q[2 * j + 1] - rr.y;
            lsum = fmaf(d1, d1, lsum);
            rp[j] = packab(-d0, -d1);
        }

        float v = lsum;
#pragma unroll
        for (int o = 16; o > 0; o >>= 1) v += __shfl_xor_sync(0xffffffffu, v, o);
        if ((tid & 31) == 0) red[tid >> 5] = v;
        __syncthreads();
        if (tid == 0) {
            float t = 0.f;
            for (int i = 0; i < 8; i++) t += red[i];
            partial[blockIdx.x * 4 + level] = t;
        }
        atomicAdd(&counts[level * 512 + tid],       hist[tid]);
        atomicAdd(&counts[level * 512 + tid + 256], hist[tid + 256]);
        __syncthreads();
    }

    float* oq = z_q + (size_t)n * 262144 + hw;
#pragma unroll
    for (int j = 0; j < 32; j++) {
        float2 rr = unpack2(rp[j]);
        oq[(2 * j) * 4096]     = __ldg(zp + (2 * j) * 4096)     - rr.x;
        oq[(2 * j + 1) * 4096] = __ldg(zp + (2 * j + 1) * 4096) - rr.y;
    }
}

__global__ void vq_zero(float* partial, int* counts)
{
    int i = blockIdx.x * 256 + threadIdx.x;
    if (i < 1024) partial[i] = 0.f;
    if (i < 2048) counts[i]  = 0;
}

__global__ void vq_finalize(const float* __restrict__ partial, const int* __restrict__ counts,
                            float* __restrict__ out_loss, float* __restrict__ out_perp)
{
    __shared__ float losses[4];
    int tid = threadIdx.x;
    if (tid < 4) {
        float e = 0.f;
        for (int b = 0; b < 256; b++) e += partial[b * 4 + tid];
        e /= (65536.f * 64.f);
        losses[tid] = 0.25f * e;
        float s = 0.f;
        for (int c = 0; c < 512; c++) {
            float pr = (float)counts[tid * 512 + c] / 65536.f;
            s += pr * logf(pr + 1e-10f);
        }
        out_perp[tid] = expf(-s);
    }
    __syncthreads();
    if (tid == 0)
        out_loss[0] = 0.25f * (losses[0] + losses[1] + losses[2] + losses[3]);
}

// ============================================================
// Host-side launch helpers
// ============================================================
static float* s_wT = nullptr;

static void launch_conv(int cfg, ConvParams& p, const float* wT, int gx, int gy)
{
    dim3 g(gx, gy);
    if (cfg == 0)      conv_gemm6<128, 8, 8><<<g, 256>>>(p, wT);
    else if (cfg == 1) conv_gemm6< 64, 8, 4><<<g, 256>>>(p, wT);
    else               conv_gemm6< 32, 4, 4><<<g, 256>>>(p, wT);
}

static void conv2d(int cfg, const float* in, const float* w, const float* bias, const float* res,
                   float* out, int N, int Cin, int IH, int IW, int Cout, int OH, int OW,
                   int KH, int KW, int stride, int pad, bool inRelu, bool outRelu)
{
    int Kdim = Cin * KH * KW;
    wtrans_kernel<<<(Kdim * Cout + 255) / 256, 256>>>(
        w, s_wT, Cout, Kdim, KH * KW, KW,
        Cin * KH * KW, KH * KW, KW, 0, 1, 0, 1);

    ConvParams p;
    p.in = in; p.bias = bias; p.residual = res; p.out = out;
    p.Cin = Cin; p.IH = IH; p.IW = IW; p.Cout = Cout; p.OH = OH; p.OW = OW;
    p.KHW = KH * KW; p.KW = KW; p.Kdim = Kdim;
    p.stride = stride; p.padH = pad; p.padW = pad;
    p.OHfull = OH; p.OWfull = OW; p.oyOff = 0; p.oyStep = 1; p.oxOff = 0; p.oxStep = 1;
    p.inRelu = inRelu ? 1 : 0; p.outRelu = outRelu ? 1 : 0; p.addRes = (res != nullptr) ? 1 : 0;

    int BMsel = (cfg == 0) ? 128 : (cfg == 1) ? 64 : 32;
    launch_conv(cfg, p, s_wT, Cout / BMsel, (N * OH * OW) / 128);
}

// ConvTranspose2d(k=4,s=2,p=1) as 4 parity-class stride-1 2x2 convs
static void convT(const float* in, const float* w, const float* bias, float* out,
                  int N, int Cin, int IH, int IW, int Cout, bool inRelu, bool outRelu)
{
    int Kdim = Cin * 4;
    for (int py = 0; py < 2; py++)
        for (int px = 0; px < 2; px++) {
            float* wT = s_wT + (py * 2 + px) * Kdim * Cout;
            wtrans_kernel<<<(Kdim * Cout + 255) / 256, 256>>>(
                w, wT, Cout, Kdim, 4, 2,
                Cin * 16, 16, 4, py, 2, px, 2);

            ConvParams p;
            p.in = in; p.bias = bias; p.residual = nullptr; p.out = out;
            p.Cin = Cin; p.IH = IH; p.IW = IW; p.Cout = Cout; p.OH = IH; p.OW = IW;
            p.KHW = 4; p.KW = 2; p.Kdim = Kdim;
            p.stride = 1; p.padH = 1 - py; p.padW = 1 - px;
            p.OHfull = 2 * IH; p.OWfull = 2 * IW;
            p.oyOff = py; p.oyStep = 2; p.oxOff = px; p.oxStep = 2;
            p.inRelu = inRelu ? 1 : 0; p.outRelu = outRelu ? 1 : 0; p.addRes = 0;
            launch_conv(0, p, wT, Cout / 128, (N * IH * IW) / 128);
        }
}

extern "C" void kernel_launch(void* const* d_in, const int* in_sizes, int n_in,
                              void* d_out, int out_size)
{
    (void)in_sizes; (void)n_in; (void)out_size;

    const float* x       = (const float*)d_in[0];
    const float* enc_w1  = (const float*)d_in[1];
    const float* enc_b1  = (const float*)d_in[2];
    const float* enc_w2  = (const float*)d_in[3];
    const float* enc_b2  = (const float*)d_in[4];
    const float* enc_w3  = (const float*)d_in[5];
    const float* enc_b3  = (const float*)d_in[6];
    const float* enc_rw1 = (const float*)d_in[7];
    const float* enc_rb1 = (const float*)d_in[8];
    const float* enc_rw2 = (const float*)d_in[9];
    const float* enc_rb2 = (const float*)d_in[10];
    const float* enc_wp  = (const float*)d_in[11];
    const float* enc_bp  = (const float*)d_in[12];
    const float* dec_w1  = (const float*)d_in[13];
    const float* dec_b1  = (const float*)d_in[14];
    const float* dec_rw1 = (const float*)d_in[15];
    const float* dec_rb1 = (const float*)d_in[16];
    const float* dec_rw2 = (const float*)d_in[17];
    const float* dec_rb2 = (const float*)d_in[18];
    const float* t1w     = (const float*)d_in[19];
    const float* t1b     = (const float*)d_in[20];
    const float* t2w     = (const float*)d_in[21];
    const float* t2b     = (const float*)d_in[22];
    const float* cbs     = (const float*)d_in[23];

    float *h1, *ga, *gb, *gmid, *gpart; int* gcnt;
    cudaGetSymbolAddress((void**)&h1,    g_h1);
    cudaGetSymbolAddress((void**)&ga,    g_a);
    cudaGetSymbolAddress((void**)&gb,    g_b);
    cudaGetSymbolAddress((void**)&gmid,  g_mid);
    cudaGetSymbolAddress((void**)&s_wT,  g_wT);
    cudaGetSymbolAddress((void**)&gpart, g_part);
    cudaGetSymbolAddress((void**)&gcnt,  g_cnt);

    cudaFuncSetAttribute(vq_kernel, cudaFuncAttributeMaxDynamicSharedMemorySize, VQ_SMEM_BYTES);

    float* out    = (float*)d_out;
    float* o_xrec = out + OFF_XREC;
    float* o_loss = out + OFF_LOSS;
    float* o_zq   = out + OFF_ZQ;
    float* o_ze   = out + OFF_ZE;
    float* o_perp = out + OFF_PERP;

    // ---------------- Encoder ----------------
    conv2d(0, x,  enc_w1, enc_b1, nullptr, h1, 16,   3, 256, 256, 128, 128, 128, 4, 4, 2, 1, false, true);
    conv2d(0, h1, enc_w2, enc_b2, nullptr, ga, 16, 128, 128, 128, 256,  64,  64, 4, 4, 2, 1, false, true);
    conv2d(0, ga, enc_w3, enc_b3, nullptr, gb, 16, 256,  64,  64, 256,  64,  64, 3, 3, 1, 1, false, false);
    // res block 0
    conv2d(2, gb,   enc_rw1,         enc_rb1,       nullptr, gmid, 16, 256, 64, 64,  32, 64, 64, 3, 3, 1, 1, true, false);
    conv2d(0, gmid, enc_rw2,         enc_rb2,       gb,      ga,   16,  32, 64, 64, 256, 64, 64, 1, 1, 1, 0, true, false);
    // res block 1
    conv2d(2, ga,   enc_rw1 + 73728, enc_rb1 + 32,  nullptr, gmid, 16, 256, 64, 64,  32, 64, 64, 3, 3, 1, 1, true, false);
    conv2d(0, gmid, enc_rw2 + 8192,  enc_rb2 + 256, ga,      gb,   16,  32, 64, 64, 256, 64, 64, 1, 1, 1, 0, true, false);
    // projection (final res-stack relu folded into inRelu) -> z_e
    conv2d(1, gb, enc_wp, enc_bp, nullptr, o_ze, 16, 256, 64, 64, 64, 64, 64, 1, 1, 1, 0, true, false);

    // ---------------- Residual VQ ----------------
    vq_zero<<<8, 256>>>(gpart, gcnt);
    vq_kernel<<<256, 256, VQ_SMEM_BYTES>>>(o_ze, cbs, o_zq, gpart, gcnt);
    vq_finalize<<<1, 128>>>(gpart, gcnt, o_loss, o_perp);

    // ---------------- Decoder ----------------
    conv2d(0, o_zq, dec_w1, dec_b1, nullptr, ga, 16, 64, 64, 64, 256, 64, 64, 3, 3, 1, 1, false, false);
    // res block 0
    conv2d(2, ga,   dec_rw1,         dec_rb1,       nullptr, gmid, 16, 256, 64, 64,  32, 64, 64, 3, 3, 1, 1, true, false);
    conv2d(0, gmid, dec_rw2,         dec_rb2,       ga,      gb,   16,  32, 64, 64, 256, 64, 64, 1, 1, 1, 0, true, false);
    // res block 1
    conv2d(2, gb,   dec_rw1 + 73728, dec_rb1 + 32,  nullptr, gmid, 16, 256, 64, 64,  32, 64, 64, 3, 3, 1, 1, true, false);
    conv2d(0, gmid, dec_rw2 + 8192,  dec_rb2 + 256, gb,      ga,   16,  32, 64, 64, 256, 64, 64, 1, 1, 1, 0, true, false);
    // conv_t1 (final res-stack relu folded in) -> relu'd [16,128,128,128]
    convT(ga, t1w, t1b, h1, 16, 256, 64, 64, 128, true, true);
    // conv_t2 -> x_recon
    convt2_kernel<<<4096, 256>>>(h1, t2w, t2b, o_xrec);
}

// round 15
// speedup vs baseline: 1.0570x; 1.0165x over previous
#include <cuda_runtime.h>
#include <math.h>
#include <stdint.h>

typedef unsigned long long u64;

// ============================================================
// Scratch (device globals -- no allocation allowed)
// ============================================================
__device__ float g_h1 [33554432];  // [16,128,128,128]
__device__ float g_a  [16777216];  // [16,256,64,64]
__device__ float g_b  [16777216];  // [16,256,64,64]
__device__ float g_mid[ 2097152];  // [16,32,64,64]
__device__ float g_wT [2304*256];  // transposed weights [K][Cout]
__device__ float g_part[256 * 4];
__device__ int   g_cnt [4 * 512];

// Output layout (tuple order): x_recon | rq_loss | z_q | z_e | perps
#define OFF_XREC 0
#define OFF_LOSS 3145728
#define OFF_ZQ   3145729
#define OFF_ZE   7340033
#define OFF_PERP 11534337

#define BK 16
#define KMAX 2304

// ---- packed fp32x2 helpers (FFMA2 path) ----
__device__ __forceinline__ u64 pack2(float x){
    u64 r; asm("mov.b64 %0, {%1, %1};" : "=l"(r) : "f"(x)); return r;
}
__device__ __forceinline__ u64 packab(float a, float b){
    u64 r; asm("mov.b64 %0, {%1, %2};" : "=l"(r) : "f"(a), "f"(b)); return r;
}
__device__ __forceinline__ void fma2(u64& acc, u64 a, u64 b){
    asm("fma.rn.f32x2 %0, %1, %2, %0;" : "+l"(acc) : "l"(a), "l"(b));
}
__device__ __forceinline__ float2 unpack2(u64 v){
    float2 f; asm("mov.b64 {%0, %1}, %2;" : "=f"(f.x), "=f"(f.y) : "l"(v)); return f;
}

struct ConvParams {
    const float* in; const float* bias; const float* residual; float* out;
    int Cin, IH, IW, Cout, OH, OW;
    int KHW, KW, Kdim;
    int stride, padH, padW;
    int OHfull, OWfull, oyOff, oyStep, oxOff, oxStep;
    int inRelu, outRelu, addRes, vecOK;
};

// ============================================================
// Weight transpose: w (arbitrary tap strides) -> wT[k][Cout]
// ============================================================
__global__ void wtrans_kernel(const float* __restrict__ w, float* __restrict__ wT,
                              int Cout, int Kdim, int KHW, int KW,
                              int wsCo, int wsCi, int wsKy,
                              int kyOff, int kyStep, int kxOff, int kxStep)
{
    int idx = blockIdx.x * 256 + threadIdx.x;
    if (idx >= Kdim * Cout) return;
    int k = idx / Cout, m = idx - k * Cout;
    int ci = k / KHW, r2 = k - ci * KHW;
    int ky = r2 / KW, kx = r2 - ky * KW;
    wT[idx] = w[m * wsCo + ci * wsCi + (kyOff + ky * kyStep) * wsKy + kxOff + kx * kxStep];
}

// ============================================================
// Implicit-GEMM conv, double-buffered, BN=128, BK=16, FFMA2,
// vectorized epilogue for aligned non-strided outputs
// ============================================================
template<int BM, int TM, int TN>
__global__ __launch_bounds__(256, 2) void conv_gemm7(ConvParams p, const float* __restrict__ wT)
{
    constexpr int NG = 128 / TN;         // n groups
    constexpr int NP = TN / 2;           // packed pairs along N
    __shared__ __align__(16) float As[2][BK][BM + 4];
    __shared__ __align__(16) float Bs[2][BK][128 + 4];
    __shared__ int sBOff[KMAX];
    __shared__ int sKyx [KMAX];

    const int tid  = threadIdx.x;
    const int Kdim = p.Kdim;

    for (int k = tid; k < Kdim; k += 256) {
        int ci = k / p.KHW, r2 = k - ci * p.KHW;
        int ky = r2 / p.KW, kx = r2 - ky * p.KW;
        sBOff[k] = (ci * p.IH + ky) * p.IW + kx;
        sKyx[k]  = (ky << 16) | kx;
    }

    const int lk   = tid >> 5;           // k-row base for loaders (rows lk, lk+8)
    const int ln4  = (tid & 31) << 2;    // 4 B-cols per thread
    const int OHOW = p.OH * p.OW;
    const int Cout = p.Cout;
    const int mBase = blockIdx.x * BM;

    // B-column precompute (4 cols per thread)
    int inB[4], iy0a[4], ix0a[4];
    {
        int colBase = blockIdx.y * 128 + ln4;
#pragma unroll
        for (int j = 0; j < 4; j++) {
            int col = colBase + j;
            int n2 = col / OHOW; int rr = col - n2 * OHOW;
            int oy = rr / p.OW;  int ox = rr - oy * p.OW;
            int iy0 = oy * p.stride - p.padH;
            int ix0 = ox * p.stride - p.padW;
            iy0a[j] = iy0; ix0a[j] = ix0;
            inB[j]  = (n2 * p.Cin * p.IH + iy0) * p.IW + ix0;
        }
    }

    u64 acc[TM][NP];
#pragma unroll
    for (int i = 0; i < TM; i++)
#pragma unroll
        for (int j = 0; j < NP; j++) acc[i][j] = 0ull;

    float4 aR[2], bR[2];

    auto loadA = [&](int k0) {
#pragma unroll
        for (int h = 0; h < 2; h++) {
            int kg = k0 + lk + h * 8;
            if constexpr (BM == 128) {
                aR[h] = *(const float4*)(wT + (size_t)kg * Cout + mBase + ((tid & 31) << 2));
            } else if constexpr (BM == 64) {
                const float2 t2 = *(const float2*)(wT + (size_t)kg * Cout + mBase + ((tid & 31) << 1));
                aR[h].x = t2.x; aR[h].y = t2.y;
            } else {
                aR[h].x = wT[(size_t)kg * Cout + mBase + (tid & 31)];
            }
        }
    };
    auto loadB = [&](int k0) {
#pragma unroll
        for (int h = 0; h < 2; h++) {
            int kg = k0 + lk + h * 8;
            int off = sBOff[kg];
            int kyx = sKyx[kg];
            int ky = kyx >> 16, kx = kyx & 0xffff;
            float v[4];
#pragma unroll
            for (int j = 0; j < 4; j++) {
                int iy = iy0a[j] + ky, ix = ix0a[j] + kx;
                float t = 0.f;
                if ((unsigned)iy < (unsigned)p.IH && (unsigned)ix < (unsigned)p.IW) {
                    t = __ldg(p.in + inB[j] + off);
                    if (p.inRelu) t = fmaxf(t, 0.f);
                }
                v[j] = t;
            }
            bR[h] = make_float4(v[0], v[1], v[2], v[3]);
        }
    };
    auto store = [&](int buf) {
#pragma unroll
        for (int h = 0; h < 2; h++) {
            if constexpr (BM == 128) {
                *(float4*)&As[buf][lk + h * 8][(tid & 31) << 2] = aR[h];
            } else if constexpr (BM == 64) {
                int m2 = (tid & 31) << 1;
                As[buf][lk + h * 8][m2] = aR[h].x; As[buf][lk + h * 8][m2 + 1] = aR[h].y;
            } else {
                As[buf][lk + h * 8][tid & 31] = aR[h].x;
            }
            *(float4*)&Bs[buf][lk + h * 8][ln4] = bR[h];
        }
    };

    __syncthreads();          // tables ready
    loadA(0); loadB(0); store(0);
    __syncthreads();

    const int nkb = Kdim / BK;
    const int tym = tid / NG;            // m group
    const int txn = tid % NG;            // n group

    for (int kb = 0; kb < nkb; kb++) {
        int cur = kb & 1;
        if (kb + 1 < nkb) { loadA((kb + 1) * BK); loadB((kb + 1) * BK); }
#pragma unroll
        for (int kk = 0; kk < BK; kk++) {
            float a[TM];
            u64 pb[NP];
#pragma unroll
            for (int s = 0; s < TM / 4; s++)
                *(float4*)&a[s * 4] = *(const float4*)&As[cur][kk][tym * TM + s * 4];
#pragma unroll
            for (int u = 0; u < NP / 2; u++) {
                ulonglong2 t = *(const ulonglong2*)&Bs[cur][kk][txn * TN + u * 4];
                pb[u * 2] = t.x; pb[u * 2 + 1] = t.y;
            }
#pragma unroll
            for (int i = 0; i < TM; i++) {
                u64 pa = pack2(a[i]);
#pragma unroll
                for (int j = 0; j < NP; j++)
                    fma2(acc[i][j], pa, pb[j]);
            }
        }
        if (kb + 1 < nkb) store(cur ^ 1);
        __syncthreads();
    }

    const size_t plane = (size_t)p.OHfull * p.OWfull;

    if (p.vecOK) {
        // ---- vectorized epilogue: TN consecutive cols per thread (16B-aligned out) ----
        int col0 = blockIdx.y * 128 + txn * TN;
        int n2 = col0 / OHOW; int rr = col0 - n2 * OHOW;
        int oy = rr / p.OW;  int ox = rr - oy * p.OW;
        size_t base = (size_t)n2 * Cout * plane + (size_t)oy * p.OWfull + ox;
#pragma unroll
        for (int i = 0; i < TM; i++) {
            int m = mBase + tym * TM + i;
            float bi = __ldg(p.bias + m);
            float vals[TN];
#pragma unroll
            for (int jp = 0; jp < NP; jp++) {
                float2 v2 = unpack2(acc[i][jp]);
                vals[2 * jp]     = v2.x + bi;
                vals[2 * jp + 1] = v2.y + bi;
            }
            size_t rowb = base + (size_t)m * plane;
#pragma unroll
            for (int q = 0; q < TN / 4; q++) {
                float4 v4 = *(float4*)&vals[q * 4];
                if (p.addRes) {
                    float4 r4 = __ldg((const float4*)(p.residual + rowb + q * 4));
                    v4.x += r4.x; v4.y += r4.y; v4.z += r4.z; v4.w += r4.w;
                }
                if (p.outRelu) {
                    v4.x = fmaxf(v4.x, 0.f); v4.y = fmaxf(v4.y, 0.f);
                    v4.z = fmaxf(v4.z, 0.f); v4.w = fmaxf(v4.w, 0.f);
                }
                *(float4*)(p.out + rowb + q * 4) = v4;
            }
        }
    } else {
        // ---- scalar epilogue (convT parity classes / unaligned outputs) ----
        int colNC[TN], colRow[TN];
#pragma unroll
        for (int j = 0; j < TN; j++) {
            int col = blockIdx.y * 128 + txn * TN + j;
            int n2 = col / OHOW; int rr = col - n2 * OHOW;
            int oy = rr / p.OW;  int ox = rr - oy * p.OW;
            colNC[j]  = n2 * Cout;
            colRow[j] = (p.oyOff + oy * p.oyStep) * p.OWfull + p.oxOff + ox * p.oxStep;
        }
#pragma unroll
        for (int i = 0; i < TM; i++) {
            int m = mBase + tym * TM + i;
            float bi = __ldg(p.bias + m);
#pragma unroll
            for (int jp = 0; jp < NP; jp++) {
                float2 v2 = unpack2(acc[i][jp]);
                float vv[2] = {v2.x, v2.y};
#pragma unroll
                for (int h = 0; h < 2; h++) {
                    int j = jp * 2 + h;
                    float v = vv[h] + bi;
                    size_t oidx = (size_t)(colNC[j] + m) * plane + colRow[j];
                    if (p.addRes) v += __ldg(p.residual + oidx);
                    if (p.outRelu) v = fmaxf(v, 0.f);
                    p.out[oidx] = v;
                }
            }
        }
    }
}

// ============================================================
// Dedicated conv_t2 (Cout=3), FFMA2 for channels 0/1
// ============================================================
__global__ __launch_bounds__(256) void convt2_kernel(
    const float* __restrict__ in, const float* __restrict__ w,
    const float* __restrict__ bias, float* __restrict__ out)
{
    __shared__ u64   sw01[128 * 16];
    __shared__ float sw2 [128 * 16];
    const int tid = threadIdx.x;
    for (int i = tid; i < 2048; i += 256) {
        sw01[i] = packab(w[i], w[2048 + i]);
        sw2[i]  = w[4096 + i];
    }
    __syncthreads();

    int idx = blockIdx.x * 256 + tid;
    int ox = idx & 255;
    int oy = (idx >> 8) & 255;
    int n  = idx >> 16;
    int py = oy & 1, px = ox & 1;
    int iyb = ((oy + py) >> 1) - 1;
    int ixb = ((ox + px) >> 1) - 1;

    u64   acc01 = packab(__ldg(bias + 0), __ldg(bias + 1));
    float acc2  = __ldg(bias + 2);
    const float* inb = in + (size_t)n * 128 * 128 * 128;

    for (int ci = 0; ci < 128; ci++) {
        const float* ic = inb + ci * 16384;
#pragma unroll
        for (int ty = 0; ty < 2; ty++) {
            int iy = iyb + ty;
            if ((unsigned)iy < 128u) {
#pragma unroll
                for (int tx2 = 0; tx2 < 2; tx2++) {
                    int ix = ixb + tx2;
                    if ((unsigned)ix < 128u) {
                        float v  = __ldg(ic + iy * 128 + ix);
                        int   wi = ci * 16 + (py + 2 * ty) * 4 + (px + 2 * tx2);
                        fma2(acc01, pack2(v), sw01[wi]);
                        acc2 = fmaf(v, sw2[wi], acc2);
                    }
                }
            }
        }
    }
    float2 a01 = unpack2(acc01);
    size_t base = (size_t)n * 3 * 65536 + oy * 256 + ox;
    out[base]             = a01.x;
    out[base + 65536]     = a01.y;
    out[base + 2 * 65536] = acc2;
}

// ============================================================
// Residual VQ -- packed f32x2 distance loop (bit-identical order)
// ============================================================
#define VQ_SMEM_BYTES ((512*64 + 512 + 512 + 32) * 4)

__global__ __launch_bounds__(256) void vq_kernel(
    const float* __restrict__ z_e, const float* __restrict__ codebooks,
    float* __restrict__ z_q, float* __restrict__ partial, int* __restrict__ counts)
{
    extern __shared__ float sh[];
    float* cb    = sh;
    float* cnorm = sh + 512 * 64;
    int*   hist  = (int*)(sh + 512 * 64 + 512);
    float* red   = sh + 512 * 64 + 512 + 512;

    const int tid = threadIdx.x;
    const int p   = blockIdx.x * 256 + tid;
    const int n   = p >> 12;
    const int hw  = p & 4095;
    const float* zp = z_e + (size_t)n * 262144 + hw;

    u64 rp[32];
#pragma unroll
    for (int j = 0; j < 32; j++)
        rp[j] = packab(__ldg(zp + (2 * j) * 4096), __ldg(zp + (2 * j + 1) * 4096));

    for (int level = 0; level < 4; level++) {
        const float4* src = (const float4*)(codebooks + (size_t)level * 32768);
        float4* dst = (float4*)cb;
        for (int i = tid; i < 8192; i += 256) dst[i] = src[i];
        hist[tid] = 0; hist[tid + 256] = 0;
        __syncthreads();
        for (int c = tid; c < 512; c += 256) {
            const float* cc = cb + c * 64;
            float s = 0.f;
#pragma unroll
            for (int d = 0; d < 64; d++) s = fmaf(cc[d], cc[d], s);
            cnorm[c] = s;
        }
        __syncthreads();

        float best = 3.0e38f; int bidx = 0;
        for (int c = 0; c < 512; c++) {
            const u64* cc = (const u64*)(cb + (c << 6));
            u64 d01 = 0ull, d23 = 0ull;
#pragma unroll
            for (int i = 0; i < 16; i++) {
                fma2(d01, cc[2 * i],     rp[2 * i]);
                fma2(d23, cc[2 * i + 1], rp[2 * i + 1]);
            }
            float2 ax = unpack2(d01), bx = unpack2(d23);
            float score = cnorm[c] - 2.f * ((ax.x + ax.y) + (bx.x + bx.y));
            if (score < best) { best = score; bidx = c; }
        }
        atomicAdd(&hist[bidx], 1);

        const float* q = cb + (bidx << 6);
        float lsum = 0.f;
#pragma unroll
        for (int j = 0; j < 32; j++) {
            float2 rr = unpack2(rp[j]);
            float d0 = q[2 * j]     - rr.x;
            lsum = fmaf(d0, d0, lsum);
            float d1 = q[2 * j + 1] - rr.y;
            lsum = fmaf(d1, d1, lsum);
            rp[j] = packab(-d0, -d1);
        }

        float v = lsum;
#pragma unroll
        for (int o = 16; o > 0; o >>= 1) v += __shfl_xor_sync(0xffffffffu, v, o);
        if ((tid & 31) == 0) red[tid >> 5] = v;
        __syncthreads();
        if (tid == 0) {
            float t = 0.f;
            for (int i = 0; i < 8; i++) t += red[i];
            partial[blockIdx.x * 4 + level] = t;
        }
        atomicAdd(&counts[level * 512 + tid],       hist[tid]);
        atomicAdd(&counts[level * 512 + tid + 256], hist[tid + 256]);
        __syncthreads();
    }

    float* oq = z_q + (size_t)n * 262144 + hw;
#pragma unroll
    for (int j = 0; j < 32; j++) {
        float2 rr = unpack2(rp[j]);
        oq[(2 * j) * 4096]     = __ldg(zp + (2 * j) * 4096)     - rr.x;
        oq[(2 * j + 1) * 4096] = __ldg(zp + (2 * j + 1) * 4096) - rr.y;
    }
}

__global__ void vq_zero(float* partial, int* counts)
{
    int i = blockIdx.x * 256 + threadIdx.x;
    if (i < 1024) partial[i] = 0.f;
    if (i < 2048) counts[i]  = 0;
}

__global__ void vq_finalize(const float* __restrict__ partial, const int* __restrict__ counts,
                            float* __restrict__ out_loss, float* __restrict__ out_perp)
{
    __shared__ float losses[4];
    int tid = threadIdx.x;
    if (tid < 4) {
        float e = 0.f;
        for (int b = 0; b < 256; b++) e += partial[b * 4 + tid];
        e /= (65536.f * 64.f);
        losses[tid] = 0.25f * e;
        float s = 0.f;
        for (int c = 0; c < 512; c++) {
            float pr = (float)counts[tid * 512 + c] / 65536.f;
            s += pr * logf(pr + 1e-10f);
        }
        out_perp[tid] = expf(-s);
    }
    __syncthreads();
    if (tid == 0)
        out_loss[0] = 0.25f * (losses[0] + losses[1] + losses[2] + losses[3]);
}

// ============================================================
// Host-side launch helpers
// ============================================================
static float* s_wT = nullptr;

static void launch_conv(int cfg, ConvParams& p, const float* wT, int gx, int gy)
{
    dim3 g(gx, gy);
    if (cfg == 0)      conv_gemm7<128, 8, 8><<<g, 256>>>(p, wT);
    else if (cfg == 1) conv_gemm7< 64, 8, 4><<<g, 256>>>(p, wT);
    else               conv_gemm7< 32, 4, 4><<<g, 256>>>(p, wT);
}

static void conv2d(int cfg, const float* in, const float* w, const float* bias, const float* res,
                   float* out, int N, int Cin, int IH, int IW, int Cout, int OH, int OW,
                   int KH, int KW, int stride, int pad, bool inRelu, bool outRelu)
{
    int Kdim = Cin * KH * KW;
    wtrans_kernel<<<(Kdim * Cout + 255) / 256, 256>>>(
        w, s_wT, Cout, Kdim, KH * KW, KW,
        Cin * KH * KW, KH * KW, KW, 0, 1, 0, 1);

    ConvParams p;
    p.in = in; p.bias = bias; p.residual = res; p.out = out;
    p.Cin = Cin; p.IH = IH; p.IW = IW; p.Cout = Cout; p.OH = OH; p.OW = OW;
    p.KHW = KH * KW; p.KW = KW; p.Kdim = Kdim;
    p.stride = stride; p.padH = pad; p.padW = pad;
    p.OHfull = OH; p.OWfull = OW; p.oyOff = 0; p.oyStep = 1; p.oxOff = 0; p.oxStep = 1;
    p.inRelu = inRelu ? 1 : 0; p.outRelu = outRelu ? 1 : 0; p.addRes = (res != nullptr) ? 1 : 0;
    // vectorized epilogue requires 16B-aligned out (and residual, if present)
    bool alignOK = (((uintptr_t)out & 15u) == 0) && (res == nullptr || (((uintptr_t)res & 15u) == 0));
    p.vecOK = alignOK ? 1 : 0;

    int BMsel = (cfg == 0) ? 128 : (cfg == 1) ? 64 : 32;
    launch_conv(cfg, p, s_wT, Cout / BMsel, (N * OH * OW) / 128);
}

// ConvTranspose2d(k=4,s=2,p=1) as 4 parity-class stride-1 2x2 convs
static void convT(const float* in, const float* w, const float* bias, float* out,
                  int N, int Cin, int IH, int IW, int Cout, bool inRelu, bool outRelu)
{
    int Kdim = Cin * 4;
    for (int py = 0; py < 2; py++)
        for (int px = 0; px < 2; px++) {
            float* wT = s_wT + (py * 2 + px) * Kdim * Cout;
            wtrans_kernel<<<(Kdim * Cout + 255) / 256, 256>>>(
                w, wT, Cout, Kdim, 4, 2,
                Cin * 16, 16, 4, py, 2, px, 2);

            ConvParams p;
            p.in = in; p.bias = bias; p.residual = nullptr; p.out = out;
            p.Cin = Cin; p.IH = IH; p.IW = IW; p.Cout = Cout; p.OH = IH; p.OW = IW;
            p.KHW = 4; p.KW = 2; p.Kdim = Kdim;
            p.stride = 1; p.padH = 1 - py; p.padW = 1 - px;
            p.OHfull = 2 * IH; p.OWfull = 2 * IW;
            p.oyOff = py; p.oyStep = 2; p.oxOff = px; p.oxStep = 2;
            p.inRelu = inRelu ? 1 : 0; p.outRelu = outRelu ? 1 : 0; p.addRes = 0;
            p.vecOK = 0;   // strided output -> scalar epilogue
            launch_conv(0, p, wT, Cout / 128, (N * IH * IW) / 128);
        }
}

extern "C" void kernel_launch(void* const* d_in, const int* in_sizes, int n_in,
                              void* d_out, int out_size)
{
    (void)in_sizes; (void)n_in; (void)out_size;

    const float* x       = (const float*)d_in[0];
    const float* enc_w1  = (const float*)d_in[1];
    const float* enc_b1  = (const float*)d_in[2];
    const float* enc_w2  = (const float*)d_in[3];
    const float* enc_b2  = (const float*)d_in[4];
    const float* enc_w3  = (const float*)d_in[5];
    const float* enc_b3  = (const float*)d_in[6];
    const float* enc_rw1 = (const float*)d_in[7];
    const float* enc_rb1 = (const float*)d_in[8];
    const float* enc_rw2 = (const float*)d_in[9];
    const float* enc_rb2 = (const float*)d_in[10];
    const float* enc_wp  = (const float*)d_in[11];
    const float* enc_bp  = (const float*)d_in[12];
    const float* dec_w1  = (const float*)d_in[13];
    const float* dec_b1  = (const float*)d_in[14];
    const float* dec_rw1 = (const float*)d_in[15];
    const float* dec_rb1 = (const float*)d_in[16];
    const float* dec_rw2 = (const float*)d_in[17];
    const float* dec_rb2 = (const float*)d_in[18];
    const float* t1w     = (const float*)d_in[19];
    const float* t1b     = (const float*)d_in[20];
    const float* t2w     = (const float*)d_in[21];
    const float* t2b     = (const float*)d_in[22];
    const float* cbs     = (const float*)d_in[23];

    float *h1, *ga, *gb, *gmid, *gpart; int* gcnt;
    cudaGetSymbolAddress((void**)&h1,    g_h1);
    cudaGetSymbolAddress((void**)&ga,    g_a);
    cudaGetSymbolAddress((void**)&gb,    g_b);
    cudaGetSymbolAddress((void**)&gmid,  g_mid);
    cudaGetSymbolAddress((void**)&s_wT,  g_wT);
    cudaGetSymbolAddress((void**)&gpart, g_part);
    cudaGetSymbolAddress((void**)&gcnt,  g_cnt);

    cudaFuncSetAttribute(vq_kernel, cudaFuncAttributeMaxDynamicSharedMemorySize, VQ_SMEM_BYTES);

    float* out    = (float*)d_out;
    float* o_xrec = out + OFF_XREC;
    float* o_loss = out + OFF_LOSS;
    float* o_zq   = out + OFF_ZQ;
    float* o_ze   = out + OFF_ZE;
    float* o_perp = out + OFF_PERP;

    // ---------------- Encoder ----------------
    conv2d(0, x,  enc_w1, enc_b1, nullptr, h1, 16,   3, 256, 256, 128, 128, 128, 4, 4, 2, 1, false, true);
    conv2d(0, h1, enc_w2, enc_b2, nullptr, ga, 16, 128, 128, 128, 256,  64,  64, 4, 4, 2, 1, false, true);
    conv2d(0, ga, enc_w3, enc_b3, nullptr, gb, 16, 256,  64,  64, 256,  64,  64, 3, 3, 1, 1, false, false);
    // res block 0
    conv2d(2, gb,   enc_rw1,         enc_rb1,       nullptr, gmid, 16, 256, 64, 64,  32, 64, 64, 3, 3, 1, 1, true, false);
    conv2d(0, gmid, enc_rw2,         enc_rb2,       gb,      ga,   16,  32, 64, 64, 256, 64, 64, 1, 1, 1, 0, true, false);
    // res block 1
    conv2d(2, ga,   enc_rw1 + 73728, enc_rb1 + 32,  nullptr, gmid, 16, 256, 64, 64,  32, 64, 64, 3, 3, 1, 1, true, false);
    conv2d(0, gmid, enc_rw2 + 8192,  enc_rb2 + 256, ga,      gb,   16,  32, 64, 64, 256, 64, 64, 1, 1, 1, 0, true, false);
    // projection (final res-stack relu folded into inRelu) -> z_e (unaligned out -> scalar epilogue)
    conv2d(1, gb, enc_wp, enc_bp, nullptr, o_ze, 16, 256, 64, 64, 64, 64, 64, 1, 1, 1, 0, true, false);

    // ---------------- Residual VQ ----------------
    vq_zero<<<8, 256>>>(gpart, gcnt);
    vq_kernel<<<256, 256, VQ_SMEM_BYTES>>>(o_ze, cbs, o_zq, gpart, gcnt);
    vq_finalize<<<1, 128>>>(gpart, gcnt, o_loss, o_perp);

    // ---------------- Decoder ----------------
    conv2d(0, o_zq, dec_w1, dec_b1, nullptr, ga, 16, 64, 64, 64, 256, 64, 64, 3, 3, 1, 1, false, false);
    // res block 0
    conv2d(2, ga,   dec_rw1,         dec_rb1,       nullptr, gmid, 16, 256, 64, 64,  32, 64, 64, 3, 3, 1, 1, true, false);
    conv2d(0, gmid, dec_rw2,         dec_rb2,       ga,      gb,   16,  32, 64, 64, 256, 64, 64, 1, 1, 1, 0, true, false);
    // res block 1
    conv2d(2, gb,   dec_rw1 + 73728, dec_rb1 + 32,  nullptr, gmid, 16, 256, 64, 64,  32, 64, 64, 3, 3, 1, 1, true, false);
    conv2d(0, gmid, dec_rw2 + 8192,  dec_rb2 + 256, gb,      ga,   16,  32, 64, 64, 256, 64, 64, 1, 1, 1, 0, true, false);
    // conv_t1 (final res-stack relu folded in) -> relu'd [16,128,128,128]
    convT(ga, t1w, t1b, h1, 16, 256, 64, 64, 128, true, true);
    // conv_t2 -> x_recon
    convt2_kernel<<<4096, 256>>>(h1, t2w, t2b, o_xrec);
}

// round 16
// speedup vs baseline: 1.0972x; 1.0380x over previous
#include <cuda_runtime.h>
#include <math.h>
#include <stdint.h>

typedef unsigned long long u64;

// ============================================================
// Scratch (device globals -- no allocation allowed)
// ============================================================
__device__ float g_h1 [33554432];
__device__ float g_a  [16777216];
__device__ float g_b  [16777216];
__device__ float g_mid[ 2097152];
__device__ float g_wT [2368*256];  // transposed weights [Kpad][Cout] (zero-padded)
__device__ float g_part[256 * 4];
__device__ int   g_cnt [4 * 512];

#define OFF_XREC 0
#define OFF_LOSS 3145728
#define OFF_ZQ   3145729
#define OFF_ZE   7340033
#define OFF_PERP 11534337

#define BK 32
#define KMAX 2304

// ---- packed fp32x2 helpers (FFMA2 path) ----
__device__ __forceinline__ u64 pack2(float x){
    u64 r; asm("mov.b64 %0, {%1, %1};" : "=l"(r) : "f"(x)); return r;
}
__device__ __forceinline__ u64 packab(float a, float b){
    u64 r; asm("mov.b64 %0, {%1, %2};" : "=l"(r) : "f"(a), "f"(b)); return r;
}
__device__ __forceinline__ void fma2(u64& acc, u64 a, u64 b){
    asm("fma.rn.f32x2 %0, %1, %2, %0;" : "+l"(acc) : "l"(a), "l"(b));
}
__device__ __forceinline__ float2 unpack2(u64 v){
    float2 f; asm("mov.b64 {%0, %1}, %2;" : "=f"(f.x), "=f"(f.y) : "l"(v)); return f;
}
__device__ __forceinline__ uint32_t smem_u32(const void* p){
    uint32_t a;
    asm("{ .reg .u64 t; cvta.to.shared.u64 t, %1; cvt.u32.u64 %0, t; }" : "=r"(a) : "l"(p));
    return a;
}
__device__ __forceinline__ void cp16(uint32_t dst, const float* src){
    asm volatile("cp.async.ca.shared.global [%0], [%1], 16;" :: "r"(dst), "l"(src));
}
__device__ __forceinline__ void cp8(uint32_t dst, const float* src){
    asm volatile("cp.async.ca.shared.global [%0], [%1], 8;" :: "r"(dst), "l"(src));
}
__device__ __forceinline__ void cp4(uint32_t dst, const float* src){
    asm volatile("cp.async.ca.shared.global [%0], [%1], 4;" :: "r"(dst), "l"(src));
}
#define CP_COMMIT() asm volatile("cp.async.commit_group;" ::: "memory")
#define CP_WAIT0()  asm volatile("cp.async.wait_group 0;" ::: "memory")

struct ConvParams {
    const float* in; const float* bias; const float* residual; float* out;
    int Cin, IH, IW, Cout, OH, OW;
    int KHW, KW, Kdim, Kpad;
    int stride, padH, padW;
    int OHfull, OWfull, oyOff, oyStep, oxOff, oxStep;
    int inRelu, outRelu, addRes, vecOK;
};

// ============================================================
// Weight transpose: w -> wT[k][Cout], zero-filled to Kpad
// ============================================================
__global__ void wtrans_kernel(const float* __restrict__ w, float* __restrict__ wT,
                              int Cout, int Kdim, int Kpad, int KHW, int KW,
                              int wsCo, int wsCi, int wsKy,
                              int kyOff, int kyStep, int kxOff, int kxStep)
{
    int idx = blockIdx.x * 256 + threadIdx.x;
    if (idx >= Kpad * Cout) return;
    int k = idx / Cout, m = idx - k * Cout;
    float v = 0.f;
    if (k < Kdim) {
        int ci = k / KHW, r2 = k - ci * KHW;
        int ky = r2 / KW, kx = r2 - ky * KW;
        v = w[m * wsCo + ci * wsCi + (kyOff + ky * kyStep) * wsKy + kxOff + kx * kxStep];
    }
    wT[idx] = v;
}

// ============================================================
// Implicit-GEMM conv: BN=128, BK=32, FFMA2, cp.async A tiles
// ============================================================
template<int BM, int TM, int TN>
__global__ __launch_bounds__(256, 2) void conv_gemm8(ConvParams p, const float* __restrict__ wT)
{
    constexpr int NG = 128 / TN;
    constexpr int NP = TN / 2;
    __shared__ __align__(16) float As[2][BK][BM + 8];
    __shared__ __align__(16) float Bs[2][BK][128 + 4];
    __shared__ int sBOff[KMAX];
    __shared__ int sKyx [KMAX];

    const int tid  = threadIdx.x;
    const int Kpad = p.Kpad;

    for (int k = tid; k < Kpad; k += 256) {
        if (k < p.Kdim) {
            int ci = k / p.KHW, r2 = k - ci * p.KHW;
            int ky = r2 / p.KW, kx = r2 - ky * p.KW;
            sBOff[k] = (ci * p.IH + ky) * p.IW + kx;
            sKyx[k]  = (ky << 16) | kx;
        } else { sBOff[k] = 0; sKyx[k] = (0x4000 << 16); }
    }

    const int lk   = tid >> 5;           // loader k-row base: rows lk + h*8, h=0..3
    const int lane = tid & 31;
    const int OHOW = p.OH * p.OW;
    const int Cout = p.Cout;
    const int mBase = blockIdx.x * BM;
    const int stride = p.stride;

    // B-column precompute: 4 consecutive cols per thread (same oy for all 4)
    int inB0, iy0, ix0;
    {
        int col = blockIdx.y * 128 + lane * 4;
        int n2 = col / OHOW; int rr = col - n2 * OHOW;
        int oy = rr / p.OW;  int ox = rr - oy * p.OW;
        iy0 = oy * stride - p.padH;
        ix0 = ox * stride - p.padW;
        inB0 = (n2 * p.Cin * p.IH + iy0) * p.IW + ix0;
    }

    u64 acc[TM][NP];
#pragma unroll
    for (int i = 0; i < TM; i++)
#pragma unroll
        for (int j = 0; j < NP; j++) acc[i][j] = 0ull;

    float4 bR[4];

    auto cpA = [&](int k0, int buf) {
#pragma unroll
        for (int h = 0; h < 4; h++) {
            int kg = k0 + lk + h * 8;
            if constexpr (BM == 128) {
                cp16(smem_u32(&As[buf][lk + h * 8][lane << 2]), wT + (size_t)kg * Cout + mBase + (lane << 2));
            } else if constexpr (BM == 64) {
                cp8(smem_u32(&As[buf][lk + h * 8][lane << 1]), wT + (size_t)kg * Cout + mBase + (lane << 1));
            } else {
                cp4(smem_u32(&As[buf][lk + h * 8][lane]), wT + (size_t)kg * Cout + mBase + lane);
            }
        }
    };
    auto loadB = [&](int k0) {
#pragma unroll
        for (int h = 0; h < 4; h++) {
            int kg = k0 + lk + h * 8;
            int off = sBOff[kg];
            int kyx = sKyx[kg];
            int ky = kyx >> 16, kx = kyx & 0xffff;
            int iy = iy0 + ky;
            float v[4];
            if ((unsigned)iy < (unsigned)p.IH) {
#pragma unroll
                for (int j = 0; j < 4; j++) {
                    int ix = ix0 + j * stride + kx;
                    float t = 0.f;
                    if ((unsigned)ix < (unsigned)p.IW) {
                        t = __ldg(p.in + inB0 + j * stride + off);
                        if (p.inRelu) t = fmaxf(t, 0.f);
                    }
                    v[j] = t;
                }
            } else {
                v[0] = v[1] = v[2] = v[3] = 0.f;
            }
            bR[h] = make_float4(v[0], v[1], v[2], v[3]);
        }
    };
    auto storeB = [&](int buf) {
#pragma unroll
        for (int h = 0; h < 4; h++)
            *(float4*)&Bs[buf][lk + h * 8][lane << 2] = bR[h];
    };

    __syncthreads();          // tables ready
    cpA(0, 0); CP_COMMIT();
    loadB(0); storeB(0);
    CP_WAIT0();
    __syncthreads();

    const int nkb = Kpad / BK;
    const int tym = tid / NG;
    const int txn = tid % NG;

    for (int kb = 0; kb < nkb; kb++) {
        int cur = kb & 1;
        if (kb + 1 < nkb) { cpA((kb + 1) * BK, cur ^ 1); CP_COMMIT(); loadB((kb + 1) * BK); }
#pragma unroll
        for (int kk = 0; kk < BK; kk++) {
            float a[TM];
            u64 pb[NP];
#pragma unroll
            for (int s = 0; s < TM / 4; s++)
                *(float4*)&a[s * 4] = *(const float4*)&As[cur][kk][tym * TM + s * 4];
#pragma unroll
            for (int u = 0; u < NP / 2; u++) {
                ulonglong2 t = *(const ulonglong2*)&Bs[cur][kk][txn * TN + u * 4];
                pb[u * 2] = t.x; pb[u * 2 + 1] = t.y;
            }
#pragma unroll
            for (int i = 0; i < TM; i++) {
                u64 pa = pack2(a[i]);
#pragma unroll
                for (int j = 0; j < NP; j++)
                    fma2(acc[i][j], pa, pb[j]);
            }
        }
        if (kb + 1 < nkb) { storeB(cur ^ 1); CP_WAIT0(); }
        __syncthreads();
    }

    const size_t plane = (size_t)p.OHfull * p.OWfull;

    if (p.vecOK) {
        int col0 = blockIdx.y * 128 + txn * TN;
        int n2 = col0 / OHOW; int rr = col0 - n2 * OHOW;
        int oy = rr / p.OW;  int ox = rr - oy * p.OW;
        size_t base = (size_t)n2 * Cout * plane + (size_t)oy * p.OWfull + ox;
#pragma unroll
        for (int i = 0; i < TM; i++) {
            int m = mBase + tym * TM + i;
            float bi = __ldg(p.bias + m);
            float vals[TN];
#pragma unroll
            for (int jp = 0; jp < NP; jp++) {
                float2 v2 = unpack2(acc[i][jp]);
                vals[2 * jp]     = v2.x + bi;
                vals[2 * jp + 1] = v2.y + bi;
            }
            size_t rowb = base + (size_t)m * plane;
#pragma unroll
            for (int q = 0; q < TN / 4; q++) {
                float4 v4 = *(float4*)&vals[q * 4];
                if (p.addRes) {
                    float4 r4 = __ldg((const float4*)(p.residual + rowb + q * 4));
                    v4.x += r4.x; v4.y += r4.y; v4.z += r4.z; v4.w += r4.w;
                }
                if (p.outRelu) {
                    v4.x = fmaxf(v4.x, 0.f); v4.y = fmaxf(v4.y, 0.f);
                    v4.z = fmaxf(v4.z, 0.f); v4.w = fmaxf(v4.w, 0.f);
                }
                *(float4*)(p.out + rowb + q * 4) = v4;
            }
        }
    } else {
        int colNC[TN], colRow[TN];
#pragma unroll
        for (int j = 0; j < TN; j++) {
            int col = blockIdx.y * 128 + txn * TN + j;
            int n2 = col / OHOW; int rr = col - n2 * OHOW;
            int oy = rr / p.OW;  int ox = rr - oy * p.OW;
            colNC[j]  = n2 * Cout;
            colRow[j] = (p.oyOff + oy * p.oyStep) * p.OWfull + p.oxOff + ox * p.oxStep;
        }
#pragma unroll
        for (int i = 0; i < TM; i++) {
            int m = mBase + tym * TM + i;
            float bi = __ldg(p.bias + m);
#pragma unroll
            for (int jp = 0; jp < NP; jp++) {
                float2 v2 = unpack2(acc[i][jp]);
                float vv[2] = {v2.x, v2.y};
#pragma unroll
                for (int h = 0; h < 2; h++) {
                    int j = jp * 2 + h;
                    float v = vv[h] + bi;
                    size_t oidx = (size_t)(colNC[j] + m) * plane + colRow[j];
                    if (p.addRes) v += __ldg(p.residual + oidx);
                    if (p.outRelu) v = fmaxf(v, 0.f);
                    p.out[oidx] = v;
                }
            }
        }
    }
}

// ============================================================
// Dedicated conv_t2 (Cout=3), FFMA2 for channels 0/1
// ============================================================
__global__ __launch_bounds__(256) void convt2_kernel(
    const float* __restrict__ in, const float* __restrict__ w,
    const float* __restrict__ bias, float* __restrict__ out)
{
    __shared__ u64   sw01[128 * 16];
    __shared__ float sw2 [128 * 16];
    const int tid = threadIdx.x;
    for (int i = tid; i < 2048; i += 256) {
        sw01[i] = packab(w[i], w[2048 + i]);
        sw2[i]  = w[4096 + i];
    }
    __syncthreads();

    int idx = blockIdx.x * 256 + tid;
    int ox = idx & 255;
    int oy = (idx >> 8) & 255;
    int n  = idx >> 16;
    int py = oy & 1, px = ox & 1;
    int iyb = ((oy + py) >> 1) - 1;
    int ixb = ((ox + px) >> 1) - 1;

    u64   acc01 = packab(__ldg(bias + 0), __ldg(bias + 1));
    float acc2  = __ldg(bias + 2);
    const float* inb = in + (size_t)n * 128 * 128 * 128;

    for (int ci = 0; ci < 128; ci++) {
        const float* ic = inb + ci * 16384;
#pragma unroll
        for (int ty = 0; ty < 2; ty++) {
            int iy = iyb + ty;
            if ((unsigned)iy < 128u) {
#pragma unroll
                for (int tx2 = 0; tx2 < 2; tx2++) {
                    int ix = ixb + tx2;
                    if ((unsigned)ix < 128u) {
                        float v  = __ldg(ic + iy * 128 + ix);
                        int   wi = ci * 16 + (py + 2 * ty) * 4 + (px + 2 * tx2);
                        fma2(acc01, pack2(v), sw01[wi]);
                        acc2 = fmaf(v, sw2[wi], acc2);
                    }
                }
            }
        }
    }
    float2 a01 = unpack2(acc01);
    size_t base = (size_t)n * 196608 + oy * 256 + ox;
    out[base]             = a01.x;
    out[base + 65536]     = a01.y;
    out[base + 131072]    = acc2;
}

// ============================================================
// Residual VQ -- packed f32x2 distance loop (bit-identical order)
// ============================================================
#define VQ_SMEM_BYTES ((512*64 + 512 + 512 + 32) * 4)

__global__ __launch_bounds__(256) void vq_kernel(
    const float* __restrict__ z_e, const float* __restrict__ codebooks,
    float* __restrict__ z_q, float* __restrict__ partial, int* __restrict__ counts)
{
    extern __shared__ float sh[];
    float* cb    = sh;
    float* cnorm = sh + 512 * 64;
    int*   hist  = (int*)(sh + 512 * 64 + 512);
    float* red   = sh + 512 * 64 + 512 + 512;

    const int tid = threadIdx.x;
    const int p   = blockIdx.x * 256 + tid;
    const int n   = p >> 12;
    const int hw  = p & 4095;
    const float* zp = z_e + (size_t)n * 262144 + hw;

    u64 rp[32];
#pragma unroll
    for (int j = 0; j < 32; j++)
        rp[j] = packab(__ldg(zp + (2 * j) * 4096), __ldg(zp + (2 * j + 1) * 4096));

    for (int level = 0; level < 4; level++) {
        const float4* src = (const float4*)(codebooks + (size_t)level * 32768);
        float4* dst = (float4*)cb;
        for (int i = tid; i < 8192; i += 256) dst[i] = src[i];
        hist[tid] = 0; hist[tid + 256] = 0;
        __syncthreads();
        for (int c = tid; c < 512; c += 256) {
            const float* cc = cb + c * 64;
            float s = 0.f;
#pragma unroll
            for (int d = 0; d < 64; d++) s = fmaf(cc[d], cc[d], s);
            cnorm[c] = s;
        }
        __syncthreads();

        float best = 3.0e38f; int bidx = 0;
        for (int c = 0; c < 512; c++) {
            const u64* cc = (const u64*)(cb + (c << 6));
            u64 d01 = 0ull, d23 = 0ull;
#pragma unroll
            for (int i = 0; i < 16; i++) {
                fma2(d01, cc[2 * i],     rp[2 * i]);
                fma2(d23, cc[2 * i + 1], rp[2 * i + 1]);
            }
            float2 ax = unpack2(d01), bx = unpack2(d23);
            float score = cnorm[c] - 2.f * ((ax.x + ax.y) + (bx.x + bx.y));
            if (score < best) { best = score; bidx = c; }
        }
        atomicAdd(&hist[bidx], 1);

        const float* q = cb + (bidx << 6);
        float lsum = 0.f;
#pragma unroll
        for (int j = 0; j < 32; j++) {
            float2 rr = unpack2(rp[j]);
            float d0 = q[2 * j]     - rr.x;
            lsum = fmaf(d0, d0, lsum);
            float d1 = q[2 * j + 1] - rr.y;
            lsum = fmaf(d1, d1, lsum);
            rp[j] = packab(-d0, -d1);
        }

        float v = lsum;
#pragma unroll
        for (int o = 16; o > 0; o >>= 1) v += __shfl_xor_sync(0xffffffffu, v, o);
        if ((tid & 31) == 0) red[tid >> 5] = v;
        __syncthreads();
        if (tid == 0) {
            float t = 0.f;
            for (int i = 0; i < 8; i++) t += red[i];
            partial[blockIdx.x * 4 + level] = t;
        }
        atomicAdd(&counts[level * 512 + tid],       hist[tid]);
        atomicAdd(&counts[level * 512 + tid + 256], hist[tid + 256]);
        __syncthreads();
    }

    float* oq = z_q + (size_t)n * 262144 + hw;
#pragma unroll
    for (int j = 0; j < 32; j++) {
        float2 rr = unpack2(rp[j]);
        oq[(2 * j) * 4096]     = __ldg(zp + (2 * j) * 4096)     - rr.x;
        oq[(2 * j + 1) * 4096] = __ldg(zp + (2 * j + 1) * 4096) - rr.y;
    }
}

__global__ void vq_zero(float* partial, int* counts)
{
    int i = blockIdx.x * 256 + threadIdx.x;
    if (i < 1024) partial[i] = 0.f;
    if (i < 2048) counts[i]  = 0;
}

__global__ void vq_finalize(const float* __restrict__ partial, const int* __restrict__ counts,
                            float* __restrict__ out_loss, float* __restrict__ out_perp)
{
    __shared__ float losses[4];
    int tid = threadIdx.x;
    if (tid < 4) {
        float e = 0.f;
        for (int b = 0; b < 256; b++) e += partial[b * 4 + tid];
        e /= (65536.f * 64.f);
        losses[tid] = 0.25f * e;
        float s = 0.f;
        for (int c = 0; c < 512; c++) {
            float pr = (float)counts[tid * 512 + c] / 65536.f;
            s += pr * logf(pr + 1e-10f);
        }
        out_perp[tid] = expf(-s);
    }
    __syncthreads();
    if (tid == 0)
        out_loss[0] = 0.25f * (losses[0] + losses[1] + losses[2] + losses[3]);
}

// ============================================================
// Host-side launch helpers
// ============================================================
static float* s_wT = nullptr;

static void launch_conv(int cfg, ConvParams& p, const float* wT, int gx, int gy)
{
    dim3 g(gx, gy);
    if (cfg == 0)      conv_gemm8<128, 8, 8><<<g, 256>>>(p, wT);
    else if (cfg == 1) conv_gemm8< 64, 8, 4><<<g, 256>>>(p, wT);
    else               conv_gemm8< 32, 4, 4><<<g, 256>>>(p, wT);
}

static void conv2d(int cfg, const float* in, const float* w, const float* bias, const float* res,
                   float* out, int N, int Cin, int IH, int IW, int Cout, int OH, int OW,
                   int KH, int KW, int stride, int pad, bool inRelu, bool outRelu)
{
    int Kdim = Cin * KH * KW;
    int Kpad = (Kdim + 31) & ~31;
    wtrans_kernel<<<(Kpad * Cout + 255) / 256, 256>>>(
        w, s_wT, Cout, Kdim, Kpad, KH * KW, KW,
        Cin * KH * KW, KH * KW, KW, 0, 1, 0, 1);

    ConvParams p;
    p.in = in; p.bias = bias; p.residual = res; p.out = out;
    p.Cin = Cin; p.IH = IH; p.IW = IW; p.Cout = Cout; p.OH = OH; p.OW = OW;
    p.KHW = KH * KW; p.KW = KW; p.Kdim = Kdim; p.Kpad = Kpad;
    p.stride = stride; p.padH = pad; p.padW = pad;
    p.OHfull = OH; p.OWfull = OW; p.oyOff = 0; p.oyStep = 1; p.oxOff = 0; p.oxStep = 1;
    p.inRelu = inRelu ? 1 : 0; p.outRelu = outRelu ? 1 : 0; p.addRes = (res != nullptr) ? 1 : 0;
    bool alignOK = (((uintptr_t)out & 15u) == 0) && (res == nullptr || (((uintptr_t)res & 15u) == 0));
    p.vecOK = alignOK ? 1 : 0;

    int BMsel = (cfg == 0) ? 128 : (cfg == 1) ? 64 : 32;
    launch_conv(cfg, p, s_wT, Cout / BMsel, (N * OH * OW) / 128);
}

// ConvTranspose2d(k=4,s=2,p=1) as 4 parity-class stride-1 2x2 convs
static void convT(const float* in, const float* w, const float* bias, float* out,
                  int N, int Cin, int IH, int IW, int Cout, bool inRelu, bool outRelu)
{
    int Kdim = Cin * 4;
    int Kpad = (Kdim + 31) & ~31;
    for (int py = 0; py < 2; py++)
        for (int px = 0; px < 2; px++) {
            float* wT = s_wT + (py * 2 + px) * Kpad * Cout;
            wtrans_kernel<<<(Kpad * Cout + 255) / 256, 256>>>(
                w, wT, Cout, Kdim, Kpad, 4, 2,
                Cin * 16, 16, 4, py, 2, px, 2);

            ConvParams p;
            p.in = in; p.bias = bias; p.residual = nullptr; p.out = out;
            p.Cin = Cin; p.IH = IH; p.IW = IW; p.Cout = Cout; p.OH = IH; p.OW = IW;
            p.KHW = 4; p.KW = 2; p.Kdim = Kdim; p.Kpad = Kpad;
            p.stride = 1; p.padH = 1 - py; p.padW = 1 - px;
            p.OHfull = 2 * IH; p.OWfull = 2 * IW;
            p.oyOff = py; p.oyStep = 2; p.oxOff = px; p.oxStep = 2;
            p.inRelu = inRelu ? 1 : 0; p.outRelu = outRelu ? 1 : 0; p.addRes = 0;
            p.vecOK = 0;
            launch_conv(0, p, wT, Cout / 128, (N * IH * IW) / 128);
        }
}

extern "C" void kernel_launch(void* const* d_in, const int* in_sizes, int n_in,
                              void* d_out, int out_size)
{
    (void)in_sizes; (void)n_in; (void)out_size;

    const float* x       = (const float*)d_in[0];
    const float* enc_w1  = (const float*)d_in[1];
    const float* enc_b1  = (const float*)d_in[2];
    const float* enc_w2  = (const float*)d_in[3];
    const float* enc_b2  = (const float*)d_in[4];
    const float* enc_w3  = (const float*)d_in[5];
    const float* enc_b3  = (const float*)d_in[6];
    const float* enc_rw1 = (const float*)d_in[7];
    const float* enc_rb1 = (const float*)d_in[8];
    const float* enc_rw2 = (const float*)d_in[9];
    const float* enc_rb2 = (const float*)d_in[10];
    const float* enc_wp  = (const float*)d_in[11];
    const float* enc_bp  = (const float*)d_in[12];
    const float* dec_w1  = (const float*)d_in[13];
    const float* dec_b1  = (const float*)d_in[14];
    const float* dec_rw1 = (const float*)d_in[15];
    const float* dec_rb1 = (const float*)d_in[16];
    const float* dec_rw2 = (const float*)d_in[17];
    const float* dec_rb2 = (const float*)d_in[18];
    const float* t1w     = (const float*)d_in[19];
    const float* t1b     = (const float*)d_in[20];
    const float* t2w     = (const float*)d_in[21];
    const float* t2b     = (const float*)d_in[22];
    const float* cbs     = (const float*)d_in[23];

    float *h1, *ga, *gb, *gmid, *gpart; int* gcnt;
    cudaGetSymbolAddress((void**)&h1,    g_h1);
    cudaGetSymbolAddress((void**)&ga,    g_a);
    cudaGetSymbolAddress((void**)&gb,    g_b);
    cudaGetSymbolAddress((void**)&gmid,  g_mid);
    cudaGetSymbolAddress((void**)&s_wT,  g_wT);
    cudaGetSymbolAddress((void**)&gpart, g_part);
    cudaGetSymbolAddress((void**)&gcnt,  g_cnt);

    cudaFuncSetAttribute(vq_kernel, cudaFuncAttributeMaxDynamicSharedMemorySize, VQ_SMEM_BYTES);

    float* out    = (float*)d_out;
    float* o_xrec = out + OFF_XREC;
    float* o_loss = out + OFF_LOSS;
    float* o_zq   = out + OFF_ZQ;
    float* o_ze   = out + OFF_ZE;
    float* o_perp = out + OFF_PERP;

    // ---------------- Encoder ----------------
    conv2d(0, x,  enc_w1, enc_b1, nullptr, h1, 16,   3, 256, 256, 128, 128, 128, 4, 4, 2, 1, false, true);
    conv2d(0, h1, enc_w2, enc_b2, nullptr, ga, 16, 128, 128, 128, 256,  64,  64, 4, 4, 2, 1, false, true);
    conv2d(0, ga, enc_w3, enc_b3, nullptr, gb, 16, 256,  64,  64, 256,  64,  64, 3, 3, 1, 1, false, false);
    // res block 0
    conv2d(2, gb,   enc_rw1,         enc_rb1,       nullptr, gmid, 16, 256, 64, 64,  32, 64, 64, 3, 3, 1, 1, true, false);
    conv2d(0, gmid, enc_rw2,         enc_rb2,       gb,      ga,   16,  32, 64, 64, 256, 64, 64, 1, 1, 1, 0, true, false);
    // res block 1
    conv2d(2, ga,   enc_rw1 + 73728, enc_rb1 + 32,  nullptr, gmid, 16, 256, 64, 64,  32, 64, 64, 3, 3, 1, 1, true, false);
    conv2d(0, gmid, enc_rw2 + 8192,  enc_rb2 + 256, ga,      gb,   16,  32, 64, 64, 256, 64, 64, 1, 1, 1, 0, true, false);
    // projection -> z_e (unaligned out -> scalar epilogue)
    conv2d(1, gb, enc_wp, enc_bp, nullptr, o_ze, 16, 256, 64, 64, 64, 64, 64, 1, 1, 1, 0, true, false);

    // ---------------- Residual VQ ----------------
    vq_zero<<<8, 256>>>(gpart, gcnt);
    vq_kernel<<<256, 256, VQ_SMEM_BYTES>>>(o_ze, cbs, o_zq, gpart, gcnt);
    vq_finalize<<<1, 128>>>(gpart, gcnt, o_loss, o_perp);

    // ---------------- Decoder ----------------
    conv2d(0, o_zq, dec_w1, dec_b1, nullptr, ga, 16, 64, 64, 64, 256, 64, 64, 3, 3, 1, 1, false, false);
    // res block 0
    conv2d(2, ga,   dec_rw1,         dec_rb1,       nullptr, gmid, 16, 256, 64, 64,  32, 64, 64, 3, 3, 1, 1, true, false);
    conv2d(0, gmid, dec_rw2,         dec_rb2,       ga,      gb,   16,  32, 64, 64, 256, 64, 64, 1, 1, 1, 0, true, false);
    // res block 1
    conv2d(2, gb,   dec_rw1 + 73728, dec_rb1 + 32,  nullptr, gmid, 16, 256, 64, 64,  32, 64, 64, 3, 3, 1, 1, true, false);
    conv2d(0, gmid, dec_rw2 + 8192,  dec_rb2 + 256, gb,      ga,   16,  32, 64, 64, 256, 64, 64, 1, 1, 1, 0, true, false);
    // conv_t1 -> relu'd [16,128,128,128]
    convT(ga, t1w, t1b, h1, 16, 256, 64, 64, 128, true, true);
    // conv_t2 -> x_recon
    convt2_kernel<<<4096, 256>>>(h1, t2w, t2b, o_xrec);
}